// round 11
// baseline (speedup 1.0000x reference)
#include <cuda_runtime.h>
#include <cuda_bf16.h>

#define CB 2
#define CS 2048
#define CD 768
#define CH 12
#define CDK 64
#define CBH 24
#define CM 4096
#define BHS 49152
#define OUT_ELEMS 3145728

typedef unsigned int u32; typedef unsigned short u16;

// bf16 hi/lo pre-split operands
__device__ u16   g_Qh[(size_t)BHS * CDK];
__device__ u16   g_Ql[(size_t)BHS * CDK];
__device__ u16   g_Kh[(size_t)BHS * CDK];
__device__ u16   g_Kl[(size_t)BHS * CDK];
__device__ u16   g_Vth[(size_t)CBH * CDK * CS];   // [bh][dk][s]
__device__ u16   g_Vtl[(size_t)CBH * CDK * CS];
__device__ float g_ctx0[(size_t)CM * CD];          // split-K partial 0
__device__ float g_ctx1[(size_t)CM * CD];          // split-K partial 1
__device__ float2 g_part[(size_t)BHS * 32];
__device__ float2 g_stats[BHS];

// ---------------- SMEM layouts ----------------
#define LDAB 72                       // bf16 row stride (144 B)
#define STAGE_LD 68                   // fp32 stage stride (16B-aligned rows)
#define OFF_AH 0u
#define OFF_AL 18432u
#define OFF_BH 36864u
#define OFF_BL 46080u
#define PR_SMEM 55296
// fusedpv layout: A region doubles as Q tile / S stage / P tile, B as K/V tile
#define FP_STATS 55296u
#define FP_SMEM (55296 + 1024)

// ---------------- helpers ----------------
__device__ __forceinline__ u32 smem_u32(const void* p) {
    u32 a;
    asm("{ .reg .u64 t; cvta.to.shared.u64 t, %1; cvt.u32.u64 %0, t; }" : "=r"(a) : "l"(p));
    return a;
}
__device__ __forceinline__ u32 cvt2(float a, float b) {  // a->low16, b->high16
    u32 r; asm("cvt.rn.bf16x2.f32 %0, %1, %2;" : "=r"(r) : "f"(b), "f"(a)); return r;
}
__device__ __forceinline__ void split_pair(float a, float b, u32& hi, u32& lo) {
    hi = cvt2(a, b);
    float ra = a - __uint_as_float(hi << 16);
    float rb = b - __uint_as_float(hi & 0xffff0000u);
    lo = cvt2(ra, rb);
}
__device__ __forceinline__ void ldm_x4(u32 addr, u32& r0, u32& r1, u32& r2, u32& r3) {
    asm volatile("ldmatrix.sync.aligned.m8n8.x4.shared.b16 {%0,%1,%2,%3}, [%4];"
                 : "=r"(r0), "=r"(r1), "=r"(r2), "=r"(r3) : "r"(addr));
}
__device__ __forceinline__ void mma16816(float* c, const u32* a, u32 b0, u32 b1) {
    asm volatile("mma.sync.aligned.m16n8k16.row.col.f32.bf16.bf16.f32 "
                 "{%0,%1,%2,%3}, {%4,%5,%6,%7}, {%8,%9}, {%0,%1,%2,%3};"
                 : "+f"(c[0]), "+f"(c[1]), "+f"(c[2]), "+f"(c[3])
                 : "r"(a[0]), "r"(a[1]), "r"(a[2]), "r"(a[3]), "r"(b0), "r"(b1));
}
__device__ __forceinline__ void cp16(u32 dst, const void* src) {
    asm volatile("cp.async.cg.shared.global [%0], [%1], 16;" :: "r"(dst), "l"(src));
}
#define CP_COMMIT() asm volatile("cp.async.commit_group;" ::: "memory")
#define CP_WAIT(n)  asm volatile("cp.async.wait_group %0;" :: "n"(n) : "memory")

// fp32 [rows x 64] (row stride rs) -> bf16 hi/lo tiles (padded stride LDAB)
__device__ __forceinline__ void fill_split(char* sp, u32 offH, u32 offL,
        const float* __restrict__ src, int rows, int rs, int tid) {
    const int total = rows * 8;
    for (int idx = tid; idx < total; idx += 256) {
        int r = idx >> 3, c = (idx & 7) * 8;
        const float* p = src + (size_t)r * rs + c;
        float4 v0 = *(const float4*)p;
        float4 v1 = *(const float4*)(p + 4);
        uint4 hv, lv;
        split_pair(v0.x, v0.y, hv.x, lv.x);
        split_pair(v0.z, v0.w, hv.y, lv.y);
        split_pair(v1.x, v1.y, hv.z, lv.z);
        split_pair(v1.z, v1.w, hv.w, lv.w);
        u32 off = (u32)(r * (LDAB * 2) + c * 2);
        *(uint4*)(sp + offH + off) = hv;
        *(uint4*)(sp + offL + off) = lv;
    }
}

// sum of two fp32 sources -> bf16 hi/lo tiles
__device__ __forceinline__ void fill_split2(char* sp, u32 offH, u32 offL,
        const float* __restrict__ s0, const float* __restrict__ s1,
        int rows, int rs, int tid) {
    const int total = rows * 8;
    for (int idx = tid; idx < total; idx += 256) {
        int r = idx >> 3, c = (idx & 7) * 8;
        const float* pa = s0 + (size_t)r * rs + c;
        const float* pb = s1 + (size_t)r * rs + c;
        float4 a0 = *(const float4*)pa;
        float4 a1 = *(const float4*)(pa + 4);
        float4 b0 = *(const float4*)pb;
        float4 b1 = *(const float4*)(pb + 4);
        a0.x += b0.x; a0.y += b0.y; a0.z += b0.z; a0.w += b0.w;
        a1.x += b1.x; a1.y += b1.y; a1.z += b1.z; a1.w += b1.w;
        uint4 hv, lv;
        split_pair(a0.x, a0.y, hv.x, lv.x);
        split_pair(a0.z, a0.w, hv.y, lv.y);
        split_pair(a1.x, a1.y, hv.z, lv.z);
        split_pair(a1.z, a1.w, hv.w, lv.w);
        u32 off = (u32)(r * (LDAB * 2) + c * 2);
        *(uint4*)(sp + offH + off) = hv;
        *(uint4*)(sp + offL + off) = lv;
    }
}

// cp.async a [rows x 64] bf16 tile pair (hi/lo, row stride rsu16)
__device__ __forceinline__ void cp_tile(u32 sb, u32 offH, u32 offL,
        const u16* __restrict__ srcH, const u16* __restrict__ srcL,
        int rows, int rsu16, int tid) {
    const int per = rows * 8;
    for (int idx = tid; idx < per * 2; idx += 256) {
        int half = idx >= per, rem = half ? idx - per : idx;
        int r = rem >> 3, c = rem & 7;
        const u16* s = (half ? srcL : srcH) + (size_t)r * rsu16 + c * 8;
        cp16(sb + (half ? offL : offH) + (u32)(r * (LDAB * 2) + c * 16), s);
    }
}

// one 64-deep k-chunk of the 128x64 block tile, bf16x3 (hh + hl + lh)
__device__ __forceinline__ void gemm_chunk(u32 sb, u32 offAH, u32 offAL,
        u32 offBH, u32 offBL, int wid, int lane, float (*acc)[4][4]) {
    const int MW = (wid >> 1) * 32, NW = (wid & 1) * 32;
    const u32 aRow = lane & 15;
    const u32 aCol = (lane >> 4) * 8;
    const u32 bRow = ((lane >> 4) << 3) + (lane & 7);
    const u32 bCol = ((lane >> 3) & 1) * 8;
#pragma unroll
    for (int ks = 0; ks < 4; ks++) {
        const u32 kb = ks * 16;
        u32 ah[2][4], al[2][4], bh[2][4], bl[2][4];
#pragma unroll
        for (int t = 0; t < 2; t++) {
            u32 ro = (MW + 16 * t + aRow) * (LDAB * 2) + (kb + aCol) * 2;
            ldm_x4(sb + offAH + ro, ah[t][0], ah[t][1], ah[t][2], ah[t][3]);
            ldm_x4(sb + offAL + ro, al[t][0], al[t][1], al[t][2], al[t][3]);
        }
#pragma unroll
        for (int g = 0; g < 2; g++) {
            u32 ro = (NW + 16 * g + bRow) * (LDAB * 2) + (kb + bCol) * 2;
            ldm_x4(sb + offBH + ro, bh[g][0], bh[g][1], bh[g][2], bh[g][3]);
            ldm_x4(sb + offBL + ro, bl[g][0], bl[g][1], bl[g][2], bl[g][3]);
        }
#pragma unroll
        for (int t = 0; t < 2; t++)
#pragma unroll
            for (int u = 0; u < 4; u++) {
                const int g = u >> 1, pr = (u & 1) * 2;
                mma16816(acc[t][u], ah[t], bh[g][pr], bh[g][pr + 1]);
                mma16816(acc[t][u], ah[t], bl[g][pr], bl[g][pr + 1]);
                mma16816(acc[t][u], al[t], bh[g][pr], bh[g][pr + 1]);
            }
    }
}

__device__ __forceinline__ void store_stage(float* stage, float (*acc)[4][4], int wid, int lane) {
    const int MW = (wid >> 1) * 32, NW = (wid & 1) * 32;
    const int r0 = lane >> 2, c0 = (lane & 3) * 2;
#pragma unroll
    for (int t = 0; t < 2; t++)
#pragma unroll
        for (int u = 0; u < 4; u++) {
            float* p0 = stage + (MW + 16 * t + r0) * STAGE_LD + NW + 8 * u + c0;
            p0[0] = acc[t][u][0];
            p0[1] = acc[t][u][1];
            float* p1 = p0 + 8 * STAGE_LD;
            p1[0] = acc[t][u][2];
            p1[1] = acc[t][u][3];
        }
}

// ---------------- Kernel: merged QKV projection (z selects Q/K/V) ----------------
__global__ void __launch_bounds__(256) proj_kernel(
    const float* __restrict__ Xq, const float* __restrict__ Xk, const float* __restrict__ Xv,
    const float* __restrict__ Wq, const float* __restrict__ Wk, const float* __restrict__ Wv,
    u16* __restrict__ Qh, u16* __restrict__ Ql,
    u16* __restrict__ Kh, u16* __restrict__ Kl,
    u16* __restrict__ Vth, u16* __restrict__ Vtl)
{
    extern __shared__ char smem[];
    u32 sb = smem_u32(smem);
    const int tid = threadIdx.x, wid = tid >> 5, lane = tid & 31;
    const int n0 = blockIdx.x * 64, m0 = blockIdx.y * 128;
    const int z = blockIdx.z;

    const float* X = (z == 0) ? Xq : (z == 1) ? Xk : Xv;
    const float* W = (z == 0) ? Wq : (z == 1) ? Wk : Wv;

    float acc[2][4][4] = {};
    for (int kc = 0; kc < 12; kc++) {
        __syncthreads();
        fill_split(smem, OFF_AH, OFF_AL, X + (size_t)m0 * CD + kc * 64, 128, CD, tid);
        fill_split(smem, OFF_BH, OFF_BL, W + (size_t)n0 * CD + kc * 64, 64, CD, tid);
        __syncthreads();
        gemm_chunk(sb, OFF_AH, OFF_AL, OFF_BH, OFF_BL, wid, lane, acc);
    }
    __syncthreads();
    float* stage = (float*)smem;
    store_stage(stage, acc, wid, lane);
    __syncthreads();

    const int b = m0 >> 11, s0 = m0 & (CS - 1), h = n0 >> 6;
    if (z < 2) {
        u16* Oh = (z == 0) ? Qh : Kh;
        u16* Ol = (z == 0) ? Ql : Kl;
        for (int r = wid; r < 128; r += 8) {
            float c0 = stage[r * STAGE_LD + 2 * lane];
            float c1 = stage[r * STAGE_LD + 2 * lane + 1];
            u32 hv, lv;
            split_pair(c0, c1, hv, lv);
            size_t off32 = ((size_t)((b * CH + h) * CS + s0 + r)) * 32;
            ((u32*)Oh)[off32 + lane] = hv;
            ((u32*)Ol)[off32 + lane] = lv;
        }
    } else {
        for (int c = wid; c < 64; c += 8) {
            size_t off32 = ((size_t)((b * CH + h) * CDK + c)) * (CS / 2) + s0 / 2;
#pragma unroll
            for (int j = 0; j < 2; j++) {
                int p = lane + 32 * j;
                float s0v = stage[(2 * p) * STAGE_LD + c];
                float s1v = stage[(2 * p + 1) * STAGE_LD + c];
                u32 hv, lv;
                split_pair(s0v, s1v, hv, lv);
                ((u32*)Vth)[off32 + p] = hv;
                ((u32*)Vtl)[off32 + p] = lv;
            }
        }
    }
}

// ---------------- Kernel: pass 1 — QK stats only (no raw write) ----------------
__global__ void __launch_bounds__(256) qkstats_kernel(
    const u16* __restrict__ Qh, const u16* __restrict__ Ql,
    const u16* __restrict__ Kh, const u16* __restrict__ Kl,
    const float* __restrict__ pos_bias, const int* __restrict__ mask,
    float2* __restrict__ part)
{
    extern __shared__ char smem[];
    u32 sb = smem_u32(smem);
    const int tid = threadIdx.x, wid = tid >> 5, lane = tid & 31;
    const int kx = blockIdx.x, kk0 = kx * 64;
    const int q0 = blockIdx.y * 128;
    const int h = blockIdx.z >> 1, b = blockIdx.z & 1;
    const int bh = b * CH + h;

    cp_tile(sb, OFF_AH, OFF_AL,
            Qh + ((size_t)bh * CS + q0) * CDK,
            Ql + ((size_t)bh * CS + q0) * CDK, 128, CDK, tid);
    cp_tile(sb, OFF_BH, OFF_BL,
            Kh + ((size_t)bh * CS + kk0) * CDK,
            Kl + ((size_t)bh * CS + kk0) * CDK, 64, CDK, tid);
    CP_COMMIT();
    CP_WAIT(0);
    __syncthreads();

    float acc[2][4][4] = {};
    gemm_chunk(sb, OFF_AH, OFF_AL, OFF_BH, OFF_BL, wid, lane, acc);
    __syncthreads();
    float* stage = (float*)smem;
    store_stage(stage, acc, wid, lane);
    __syncthreads();

    const int halfl = lane >> 4;
    const int cq = (lane & 15) * 4;
#pragma unroll
    for (int it = 0; it < 8; it++) {
        const int r = wid * 16 + it * 2 + halfl;
        const int q = q0 + r;
        float4 pb = *(const float4*)(pos_bias + ((size_t)(h * CS + q)) * CS + kk0 + cq);
        int4   mk = *(const int4*)(mask + ((size_t)(b * CS + q)) * CS + kk0 + cq);
        float4 sv = *(const float4*)(stage + r * STAGE_LD + cq);
        float4 rv;
        rv.x = (mk.x == 0) ? -1e9f : sv.x * 0.125f + pb.x;
        rv.y = (mk.y == 0) ? -1e9f : sv.y * 0.125f + pb.y;
        rv.z = (mk.z == 0) ? -1e9f : sv.z * 0.125f + pb.z;
        rv.w = (mk.w == 0) ? -1e9f : sv.w * 0.125f + pb.w;

        float mx = fmaxf(fmaxf(rv.x, rv.y), fmaxf(rv.z, rv.w));
#pragma unroll
        for (int o = 8; o > 0; o >>= 1) mx = fmaxf(mx, __shfl_xor_sync(0xffffffffu, mx, o));
        float se = __expf(rv.x - mx) + __expf(rv.y - mx) +
                   __expf(rv.z - mx) + __expf(rv.w - mx);
#pragma unroll
        for (int o = 8; o > 0; o >>= 1) se += __shfl_xor_sync(0xffffffffu, se, o);
        if ((lane & 15) == 0)
            part[((size_t)(bh * CS + q)) * 32 + kx] = make_float2(mx, se);
    }
}

// ---------------- Kernel: reduce partials -> (max, 1/sum) ----------------
__global__ void __launch_bounds__(256) reduce_kernel(
    const float2* __restrict__ part, float2* __restrict__ stats)
{
    const int wid = threadIdx.x >> 5, lane = threadIdx.x & 31;
    const int row = blockIdx.x * 8 + wid;
    float2 p = part[(size_t)row * 32 + lane];
    float M = p.x;
#pragma unroll
    for (int o = 16; o > 0; o >>= 1) M = fmaxf(M, __shfl_xor_sync(0xffffffffu, M, o));
    float s = p.y * __expf(p.x - M);
#pragma unroll
    for (int o = 16; o > 0; o >>= 1) s += __shfl_xor_sync(0xffffffffu, s, o);
    if (lane == 0) stats[row] = make_float2(M, 1.0f / s);
}

// ---------------- Kernel: pass 2 — recompute QK, write attn, accumulate PV ----------------
// A region (OFF_AH/OFF_AL): Q tile -> S stage -> P tile per chunk.
// B region (OFF_BH/OFF_BL): K tile -> V tile per chunk.
__global__ void __launch_bounds__(256) fusedpv_kernel(
    const u16* __restrict__ Qh, const u16* __restrict__ Ql,
    const u16* __restrict__ Kh, const u16* __restrict__ Kl,
    const u16* __restrict__ Vth, const u16* __restrict__ Vtl,
    const float* __restrict__ pos_bias, const int* __restrict__ mask,
    const float2* __restrict__ stats, float* __restrict__ attn,
    float* __restrict__ ctx0, float* __restrict__ ctx1)
{
    extern __shared__ char smem[];
    u32 sb = smem_u32(smem);
    const int tid = threadIdx.x, wid = tid >> 5, lane = tid & 31;
    const int q0 = blockIdx.x * 128;
    const int kseg = blockIdx.y;
    const int h = blockIdx.z >> 1, b = blockIdx.z & 1;
    const int bh = b * CH + h;
    const int kbase = kseg * 16;

    float* smax = (float*)(smem + FP_STATS);
    float* sinv = smax + 128;
    if (tid < 128) {
        float2 st = stats[(size_t)bh * CS + q0 + tid];
        smax[tid] = st.x;
        sinv[tid] = st.y;
    }

    const u16* qhp = Qh + ((size_t)bh * CS + q0) * CDK;
    const u16* qlp = Ql + ((size_t)bh * CS + q0) * CDK;
    cp_tile(sb, OFF_AH, OFF_AL, qhp, qlp, 128, CDK, tid);
    cp_tile(sb, OFF_BH, OFF_BL,
            Kh + ((size_t)bh * CS + kbase * 64) * CDK,
            Kl + ((size_t)bh * CS + kbase * 64) * CDK, 64, CDK, tid);
    CP_COMMIT();

    const int rb = tid >> 4, cg = (tid & 15) * 4;
    float accp[2][4][4] = {};
    float* stage = (float*)smem;

    for (int i = 0; i < 16; i++) {
        const int kc = kbase + i;
        CP_WAIT(0);
        __syncthreads();

        // QK chunk
        float accs[2][4][4] = {};
        gemm_chunk(sb, OFF_AH, OFF_AL, OFF_BH, OFF_BL, wid, lane, accs);
        __syncthreads();

        // prefetch V into B (K consumed)
        cp_tile(sb, OFF_BH, OFF_BL,
                Vth + (size_t)bh * CDK * CS + kc * 64,
                Vtl + (size_t)bh * CDK * CS + kc * 64, 64, CS, tid);
        CP_COMMIT();

        store_stage(stage, accs, wid, lane);
        __syncthreads();

        // epilogue: bias+mask, normalize, write final attn, keep P in regs
        float4 pw[8];
#pragma unroll
        for (int p = 0; p < 8; p++) {
            const int row = p * 16 + rb;
            const int q = q0 + row;
            float4 sv = *(const float4*)(stage + row * STAGE_LD + cg);
            float4 pb = *(const float4*)(pos_bias + ((size_t)(h * CS + q)) * CS + kc * 64 + cg);
            int4   mk = *(const int4*)(mask + ((size_t)(b * CS + q)) * CS + kc * 64 + cg);
            float4 rv;
            rv.x = (mk.x == 0) ? -1e9f : sv.x * 0.125f + pb.x;
            rv.y = (mk.y == 0) ? -1e9f : sv.y * 0.125f + pb.y;
            rv.z = (mk.z == 0) ? -1e9f : sv.z * 0.125f + pb.z;
            rv.w = (mk.w == 0) ? -1e9f : sv.w * 0.125f + pb.w;
            const float mx = smax[row], iv = sinv[row];
            float4 w;
            w.x = __expf(rv.x - mx) * iv;
            w.y = __expf(rv.y - mx) * iv;
            w.z = __expf(rv.z - mx) * iv;
            w.w = __expf(rv.w - mx) * iv;
            __stcs((float4*)(attn + ((size_t)(bh * CS + q)) * CS + kc * 64 + cg), w);
            pw[p] = w;
        }
        __syncthreads();   // all stage reads done before P overwrites A

#pragma unroll
        for (int p = 0; p < 8; p++) {
            const int row = p * 16 + rb;
            uint2 hv, lv;
            split_pair(pw[p].x, pw[p].y, hv.x, lv.x);
            split_pair(pw[p].z, pw[p].w, hv.y, lv.y);
            u32 off = (u32)(row * (LDAB * 2) + cg * 2);
            *(uint2*)(smem + OFF_AH + off) = hv;
            *(uint2*)(smem + OFF_AL + off) = lv;
        }
        CP_WAIT(0);        // V ready
        __syncthreads();

        // PV chunk
        gemm_chunk(sb, OFF_AH, OFF_AL, OFF_BH, OFF_BL, wid, lane, accp);
        __syncthreads();

        if (i < 15) {      // next Q + K
            cp_tile(sb, OFF_AH, OFF_AL, qhp, qlp, 128, CDK, tid);
            cp_tile(sb, OFF_BH, OFF_BL,
                    Kh + ((size_t)bh * CS + (kc + 1) * 64) * CDK,
                    Kl + ((size_t)bh * CS + (kc + 1) * 64) * CDK, 64, CDK, tid);
            CP_COMMIT();
        }
    }

    store_stage(stage, accp, wid, lane);
    __syncthreads();

    float* ctx = kseg ? ctx1 : ctx0;
    for (int r = wid; r < 128; r += 8) {
        size_t off = ((size_t)(b * CS + q0 + r)) * CD + h * CDK;
        ctx[off + lane]      = stage[r * STAGE_LD + lane];
        ctx[off + 32 + lane] = stage[r * STAGE_LD + 32 + lane];
    }
}

// ---------------- Kernel: output projection (sums split-K partials) ----------------
__global__ void __launch_bounds__(256) outproj_kernel(
    const float* __restrict__ ctx0, const float* __restrict__ ctx1,
    const float* __restrict__ W,
    const float* __restrict__ bias, float* __restrict__ out)
{
    extern __shared__ char smem[];
    u32 sb = smem_u32(smem);
    const int tid = threadIdx.x, wid = tid >> 5, lane = tid & 31;
    const int n0 = blockIdx.x * 64, m0 = blockIdx.y * 128;

    float acc[2][4][4] = {};
    for (int kc = 0; kc < 12; kc++) {
        __syncthreads();
        fill_split2(smem, OFF_AH, OFF_AL,
                    ctx0 + (size_t)m0 * CD + kc * 64,
                    ctx1 + (size_t)m0 * CD + kc * 64, 128, CD, tid);
        fill_split(smem, OFF_BH, OFF_BL, W + (size_t)n0 * CD + kc * 64, 64, CD, tid);
        __syncthreads();
        gemm_chunk(sb, OFF_AH, OFF_AL, OFF_BH, OFF_BL, wid, lane, acc);
    }
    __syncthreads();
    float* stage = (float*)smem;
    store_stage(stage, acc, wid, lane);
    __syncthreads();

    float b0 = bias[n0 + lane];
    float b1 = bias[n0 + 32 + lane];
    for (int r = wid; r < 128; r += 8) {
        size_t off = (size_t)(m0 + r) * CD + n0;
        out[off + lane]      = stage[r * STAGE_LD + lane] + b0;
        out[off + 32 + lane] = stage[r * STAGE_LD + 32 + lane] + b1;
    }
}

// ---------------------------------------------------------------------------
extern "C" void kernel_launch(void* const* d_in, const int* in_sizes, int n_in,
                              void* d_out, int out_size)
{
    (void)in_sizes; (void)n_in; (void)out_size;
    const float* query    = (const float*)d_in[0];
    const float* key      = (const float*)d_in[1];
    const float* value    = (const float*)d_in[2];
    const int*   mask     = (const int*)d_in[3];
    const float* pos_bias = (const float*)d_in[4];
    const float* Wq       = (const float*)d_in[5];
    const float* Wk       = (const float*)d_in[6];
    const float* Wv       = (const float*)d_in[7];
    const float* Wo       = (const float*)d_in[8];
    const float* bo       = (const float*)d_in[9];

    float* out  = (float*)d_out;
    float* attn = out + OUT_ELEMS;

    u16 *pQh, *pQl, *pKh, *pKl, *pVth, *pVtl;
    float *pC0, *pC1;
    float2 *pPart, *pStats;
    cudaGetSymbolAddress((void**)&pQh,  g_Qh);
    cudaGetSymbolAddress((void**)&pQl,  g_Ql);
    cudaGetSymbolAddress((void**)&pKh,  g_Kh);
    cudaGetSymbolAddress((void**)&pKl,  g_Kl);
    cudaGetSymbolAddress((void**)&pVth, g_Vth);
    cudaGetSymbolAddress((void**)&pVtl, g_Vtl);
    cudaGetSymbolAddress((void**)&pC0,  g_ctx0);
    cudaGetSymbolAddress((void**)&pC1,  g_ctx1);
    cudaGetSymbolAddress((void**)&pPart,  g_part);
    cudaGetSymbolAddress((void**)&pStats, g_stats);

    cudaFuncSetAttribute(proj_kernel,    cudaFuncAttributeMaxDynamicSharedMemorySize, PR_SMEM);
    cudaFuncSetAttribute(qkstats_kernel, cudaFuncAttributeMaxDynamicSharedMemorySize, PR_SMEM);
    cudaFuncSetAttribute(fusedpv_kernel, cudaFuncAttributeMaxDynamicSharedMemorySize, FP_SMEM);
    cudaFuncSetAttribute(outproj_kernel, cudaFuncAttributeMaxDynamicSharedMemorySize, PR_SMEM);

    dim3 gProj(CD / 64, CM / 128, 3);          // (12, 32, 3)
    proj_kernel<<<gProj, 256, PR_SMEM>>>(query, key, value, Wq, Wk, Wv,
                                         pQh, pQl, pKh, pKl, pVth, pVtl);

    dim3 gStats(CS / 64, CS / 128, CBH);       // (32, 16, 24), z = h*2+b
    qkstats_kernel<<<gStats, 256, PR_SMEM>>>(pQh, pQl, pKh, pKl,
                                             pos_bias, mask, pPart);

    reduce_kernel<<<BHS / 8, 256>>>(pPart, pStats);

    dim3 gFP(CS / 128, 2, CBH);                // (16, 2, 24) split-K, z = h*2+b
    fusedpv_kernel<<<gFP, 256, FP_SMEM>>>(pQh, pQl, pKh, pKl, pVth, pVtl,
                                          pos_bias, mask, pStats, attn, pC0, pC1);

    dim3 gOut(CD / 64, CM / 128);              // (12, 32)
    outproj_kernel<<<gOut, 256, PR_SMEM>>>(pC0, pC1, Wo, bo, out);
}

// round 15
// speedup vs baseline: 1.2228x; 1.2228x over previous
#include <cuda_runtime.h>
#include <cuda_bf16.h>

#define CB 2
#define CS 2048
#define CD 768
#define CH 12
#define CDK 64
#define CBH 24
#define CM 4096
#define BHS 49152
#define OUT_ELEMS 3145728

typedef unsigned int u32; typedef unsigned short u16;

// bf16 hi/lo pre-split operands
__device__ u16   g_Qh[(size_t)BHS * CDK];
__device__ u16   g_Ql[(size_t)BHS * CDK];
__device__ u16   g_Kh[(size_t)BHS * CDK];
__device__ u16   g_Kl[(size_t)BHS * CDK];
__device__ u16   g_Vth[(size_t)CBH * CDK * CS];   // [bh][dk][s]
__device__ u16   g_Vtl[(size_t)CBH * CDK * CS];
__device__ float g_ctx0[(size_t)CM * CD];          // split-K partial 0
__device__ float g_ctx1[(size_t)CM * CD];          // split-K partial 1
__device__ float2 g_part[(size_t)BHS * 32];
__device__ float2 g_stats[BHS];

// ---------------- SMEM layouts ----------------
#define LDAB 72                       // bf16 row stride (144 B)
#define STAGE_LD 68                   // fp32 stage stride (16B-aligned rows)
#define OFF_AH 0u
#define OFF_AL 18432u
#define OFF_BH 36864u
#define OFF_BL 46080u
#define PR_SMEM 55296
// pv layout: single V buffer; stage overlaps P region after the loop
#define PV_PH 0u
#define PV_PL 18432u
#define PV_VHO 36864u
#define PV_VLO 46080u
#define PV_STATS 55296u
#define PV_SMEM (55296 + 1024)

// ---------------- helpers ----------------
__device__ __forceinline__ u32 smem_u32(const void* p) {
    u32 a;
    asm("{ .reg .u64 t; cvta.to.shared.u64 t, %1; cvt.u32.u64 %0, t; }" : "=r"(a) : "l"(p));
    return a;
}
__device__ __forceinline__ u32 cvt2(float a, float b) {  // a->low16, b->high16
    u32 r; asm("cvt.rn.bf16x2.f32 %0, %1, %2;" : "=r"(r) : "f"(b), "f"(a)); return r;
}
__device__ __forceinline__ void split_pair(float a, float b, u32& hi, u32& lo) {
    hi = cvt2(a, b);
    float ra = a - __uint_as_float(hi << 16);
    float rb = b - __uint_as_float(hi & 0xffff0000u);
    lo = cvt2(ra, rb);
}
__device__ __forceinline__ void ldm_x4(u32 addr, u32& r0, u32& r1, u32& r2, u32& r3) {
    asm volatile("ldmatrix.sync.aligned.m8n8.x4.shared.b16 {%0,%1,%2,%3}, [%4];"
                 : "=r"(r0), "=r"(r1), "=r"(r2), "=r"(r3) : "r"(addr));
}
__device__ __forceinline__ void mma16816(float* c, const u32* a, u32 b0, u32 b1) {
    asm volatile("mma.sync.aligned.m16n8k16.row.col.f32.bf16.bf16.f32 "
                 "{%0,%1,%2,%3}, {%4,%5,%6,%7}, {%8,%9}, {%0,%1,%2,%3};"
                 : "+f"(c[0]), "+f"(c[1]), "+f"(c[2]), "+f"(c[3])
                 : "r"(a[0]), "r"(a[1]), "r"(a[2]), "r"(a[3]), "r"(b0), "r"(b1));
}
__device__ __forceinline__ void cp16(u32 dst, const void* src) {
    asm volatile("cp.async.cg.shared.global [%0], [%1], 16;" :: "r"(dst), "l"(src));
}
#define CP_COMMIT() asm volatile("cp.async.commit_group;" ::: "memory")
#define CP_WAIT(n)  asm volatile("cp.async.wait_group %0;" :: "n"(n) : "memory")

// fp32 [rows x 64] (row stride rs) -> bf16 hi/lo tiles (padded stride LDAB)
__device__ __forceinline__ void fill_split(char* sp, u32 offH, u32 offL,
        const float* __restrict__ src, int rows, int rs, int tid) {
    const int total = rows * 8;
    for (int idx = tid; idx < total; idx += 256) {
        int r = idx >> 3, c = (idx & 7) * 8;
        const float* p = src + (size_t)r * rs + c;
        float4 v0 = *(const float4*)p;
        float4 v1 = *(const float4*)(p + 4);
        uint4 hv, lv;
        split_pair(v0.x, v0.y, hv.x, lv.x);
        split_pair(v0.z, v0.w, hv.y, lv.y);
        split_pair(v1.x, v1.y, hv.z, lv.z);
        split_pair(v1.z, v1.w, hv.w, lv.w);
        u32 off = (u32)(r * (LDAB * 2) + c * 2);
        *(uint4*)(sp + offH + off) = hv;
        *(uint4*)(sp + offL + off) = lv;
    }
}

// sum of two fp32 sources -> bf16 hi/lo tiles
__device__ __forceinline__ void fill_split2(char* sp, u32 offH, u32 offL,
        const float* __restrict__ s0, const float* __restrict__ s1,
        int rows, int rs, int tid) {
    const int total = rows * 8;
    for (int idx = tid; idx < total; idx += 256) {
        int r = idx >> 3, c = (idx & 7) * 8;
        const float* pa = s0 + (size_t)r * rs + c;
        const float* pb = s1 + (size_t)r * rs + c;
        float4 a0 = *(const float4*)pa;
        float4 a1 = *(const float4*)(pa + 4);
        float4 b0 = *(const float4*)pb;
        float4 b1 = *(const float4*)(pb + 4);
        a0.x += b0.x; a0.y += b0.y; a0.z += b0.z; a0.w += b0.w;
        a1.x += b1.x; a1.y += b1.y; a1.z += b1.z; a1.w += b1.w;
        uint4 hv, lv;
        split_pair(a0.x, a0.y, hv.x, lv.x);
        split_pair(a0.z, a0.w, hv.y, lv.y);
        split_pair(a1.x, a1.y, hv.z, lv.z);
        split_pair(a1.z, a1.w, hv.w, lv.w);
        u32 off = (u32)(r * (LDAB * 2) + c * 2);
        *(uint4*)(sp + offH + off) = hv;
        *(uint4*)(sp + offL + off) = lv;
    }
}

// cp.async a [rows x 64] bf16 tile pair (hi/lo, row stride rsu16)
__device__ __forceinline__ void cp_tile(u32 sb, u32 offH, u32 offL,
        const u16* __restrict__ srcH, const u16* __restrict__ srcL,
        int rows, int rsu16, int tid) {
    const int per = rows * 8;
    for (int idx = tid; idx < per * 2; idx += 256) {
        int half = idx >= per, rem = half ? idx - per : idx;
        int r = rem >> 3, c = rem & 7;
        const u16* s = (half ? srcL : srcH) + (size_t)r * rsu16 + c * 8;
        cp16(sb + (half ? offL : offH) + (u32)(r * (LDAB * 2) + c * 16), s);
    }
}

// one 64-deep k-chunk of the 128x64 block tile, bf16x3 (hh + hl + lh)
__device__ __forceinline__ void gemm_chunk(u32 sb, u32 offAH, u32 offAL,
        u32 offBH, u32 offBL, int wid, int lane, float (*acc)[4][4]) {
    const int MW = (wid >> 1) * 32, NW = (wid & 1) * 32;
    const u32 aRow = lane & 15;
    const u32 aCol = (lane >> 4) * 8;
    const u32 bRow = ((lane >> 4) << 3) + (lane & 7);
    const u32 bCol = ((lane >> 3) & 1) * 8;
#pragma unroll
    for (int ks = 0; ks < 4; ks++) {
        const u32 kb = ks * 16;
        u32 ah[2][4], al[2][4], bh[2][4], bl[2][4];
#pragma unroll
        for (int t = 0; t < 2; t++) {
            u32 ro = (MW + 16 * t + aRow) * (LDAB * 2) + (kb + aCol) * 2;
            ldm_x4(sb + offAH + ro, ah[t][0], ah[t][1], ah[t][2], ah[t][3]);
            ldm_x4(sb + offAL + ro, al[t][0], al[t][1], al[t][2], al[t][3]);
        }
#pragma unroll
        for (int g = 0; g < 2; g++) {
            u32 ro = (NW + 16 * g + bRow) * (LDAB * 2) + (kb + bCol) * 2;
            ldm_x4(sb + offBH + ro, bh[g][0], bh[g][1], bh[g][2], bh[g][3]);
            ldm_x4(sb + offBL + ro, bl[g][0], bl[g][1], bl[g][2], bl[g][3]);
        }
#pragma unroll
        for (int t = 0; t < 2; t++)
#pragma unroll
            for (int u = 0; u < 4; u++) {
                const int g = u >> 1, pr = (u & 1) * 2;
                mma16816(acc[t][u], ah[t], bh[g][pr], bh[g][pr + 1]);
                mma16816(acc[t][u], ah[t], bl[g][pr], bl[g][pr + 1]);
                mma16816(acc[t][u], al[t], bh[g][pr], bh[g][pr + 1]);
            }
    }
}

__device__ __forceinline__ void store_stage(float* stage, float (*acc)[4][4], int wid, int lane) {
    const int MW = (wid >> 1) * 32, NW = (wid & 1) * 32;
    const int r0 = lane >> 2, c0 = (lane & 3) * 2;
#pragma unroll
    for (int t = 0; t < 2; t++)
#pragma unroll
        for (int u = 0; u < 4; u++) {
            float* p0 = stage + (MW + 16 * t + r0) * STAGE_LD + NW + 8 * u + c0;
            p0[0] = acc[t][u][0];
            p0[1] = acc[t][u][1];
            float* p1 = p0 + 8 * STAGE_LD;
            p1[0] = acc[t][u][2];
            p1[1] = acc[t][u][3];
        }
}

// ---------------- Kernel: merged QKV projection (z selects Q/K/V) ----------------
__global__ void __launch_bounds__(256) proj_kernel(
    const float* __restrict__ Xq, const float* __restrict__ Xk, const float* __restrict__ Xv,
    const float* __restrict__ Wq, const float* __restrict__ Wk, const float* __restrict__ Wv,
    u16* __restrict__ Qh, u16* __restrict__ Ql,
    u16* __restrict__ Kh, u16* __restrict__ Kl,
    u16* __restrict__ Vth, u16* __restrict__ Vtl)
{
    extern __shared__ char smem[];
    u32 sb = smem_u32(smem);
    const int tid = threadIdx.x, wid = tid >> 5, lane = tid & 31;
    const int n0 = blockIdx.x * 64, m0 = blockIdx.y * 128;
    const int z = blockIdx.z;

    const float* X = (z == 0) ? Xq : (z == 1) ? Xk : Xv;
    const float* W = (z == 0) ? Wq : (z == 1) ? Wk : Wv;

    float acc[2][4][4] = {};
    for (int kc = 0; kc < 12; kc++) {
        __syncthreads();
        fill_split(smem, OFF_AH, OFF_AL, X + (size_t)m0 * CD + kc * 64, 128, CD, tid);
        fill_split(smem, OFF_BH, OFF_BL, W + (size_t)n0 * CD + kc * 64, 64, CD, tid);
        __syncthreads();
        gemm_chunk(sb, OFF_AH, OFF_AL, OFF_BH, OFF_BL, wid, lane, acc);
    }
    __syncthreads();
    float* stage = (float*)smem;
    store_stage(stage, acc, wid, lane);
    __syncthreads();

    const int b = m0 >> 11, s0 = m0 & (CS - 1), h = n0 >> 6;
    if (z < 2) {
        u16* Oh = (z == 0) ? Qh : Kh;
        u16* Ol = (z == 0) ? Ql : Kl;
        for (int r = wid; r < 128; r += 8) {
            float c0 = stage[r * STAGE_LD + 2 * lane];
            float c1 = stage[r * STAGE_LD + 2 * lane + 1];
            u32 hv, lv;
            split_pair(c0, c1, hv, lv);
            size_t off32 = ((size_t)((b * CH + h) * CS + s0 + r)) * 32;
            ((u32*)Oh)[off32 + lane] = hv;
            ((u32*)Ol)[off32 + lane] = lv;
        }
    } else {
        for (int c = wid; c < 64; c += 8) {
            size_t off32 = ((size_t)((b * CH + h) * CDK + c)) * (CS / 2) + s0 / 2;
#pragma unroll
            for (int j = 0; j < 2; j++) {
                int p = lane + 32 * j;
                float s0v = stage[(2 * p) * STAGE_LD + c];
                float s1v = stage[(2 * p + 1) * STAGE_LD + c];
                u32 hv, lv;
                split_pair(s0v, s1v, hv, lv);
                ((u32*)Vth)[off32 + p] = hv;
                ((u32*)Vtl)[off32 + p] = lv;
            }
        }
    }
}

// ---------------- Kernel: scores (z = h*2+b for pos_bias L2 reuse) ----------------
__global__ void __launch_bounds__(256) scores_kernel(
    const u16* __restrict__ Qh, const u16* __restrict__ Ql,
    const u16* __restrict__ Kh, const u16* __restrict__ Kl,
    const float* __restrict__ pos_bias, const int* __restrict__ mask,
    float* __restrict__ raw, float2* __restrict__ part)
{
    extern __shared__ char smem[];
    u32 sb = smem_u32(smem);
    const int tid = threadIdx.x, wid = tid >> 5, lane = tid & 31;
    const int kx = blockIdx.x, kk0 = kx * 64;
    const int q0 = blockIdx.y * 128;
    const int h = blockIdx.z >> 1, b = blockIdx.z & 1;
    const int bh = b * CH + h;

    cp_tile(sb, OFF_AH, OFF_AL,
            Qh + ((size_t)bh * CS + q0) * CDK,
            Ql + ((size_t)bh * CS + q0) * CDK, 128, CDK, tid);
    cp_tile(sb, OFF_BH, OFF_BL,
            Kh + ((size_t)bh * CS + kk0) * CDK,
            Kl + ((size_t)bh * CS + kk0) * CDK, 64, CDK, tid);
    CP_COMMIT();
    CP_WAIT(0);
    __syncthreads();

    float acc[2][4][4] = {};
    gemm_chunk(sb, OFF_AH, OFF_AL, OFF_BH, OFF_BL, wid, lane, acc);
    __syncthreads();
    float* stage = (float*)smem;
    store_stage(stage, acc, wid, lane);
    __syncthreads();

    const int halfl = lane >> 4;
    const int cq = (lane & 15) * 4;
#pragma unroll
    for (int it = 0; it < 8; it++) {
        const int r = wid * 16 + it * 2 + halfl;
        const int q = q0 + r;
        float4 pb = *(const float4*)(pos_bias + ((size_t)(h * CS + q)) * CS + kk0 + cq);
        int4   mk = *(const int4*)(mask + ((size_t)(b * CS + q)) * CS + kk0 + cq);
        float4 sv = *(const float4*)(stage + r * STAGE_LD + cq);
        float4 rv;
        rv.x = (mk.x == 0) ? -1e9f : sv.x * 0.125f + pb.x;
        rv.y = (mk.y == 0) ? -1e9f : sv.y * 0.125f + pb.y;
        rv.z = (mk.z == 0) ? -1e9f : sv.z * 0.125f + pb.z;
        rv.w = (mk.w == 0) ? -1e9f : sv.w * 0.125f + pb.w;
        __stcs((float4*)(raw + ((size_t)(bh * CS + q)) * CS + kk0 + cq), rv);

        float mx = fmaxf(fmaxf(rv.x, rv.y), fmaxf(rv.z, rv.w));
#pragma unroll
        for (int o = 8; o > 0; o >>= 1) mx = fmaxf(mx, __shfl_xor_sync(0xffffffffu, mx, o));
        float se = __expf(rv.x - mx) + __expf(rv.y - mx) +
                   __expf(rv.z - mx) + __expf(rv.w - mx);
#pragma unroll
        for (int o = 8; o > 0; o >>= 1) se += __shfl_xor_sync(0xffffffffu, se, o);
        if ((lane & 15) == 0)
            part[((size_t)(bh * CS + q)) * 32 + kx] = make_float2(mx, se);
    }
}

// ---------------- Kernel: reduce partials -> (max, 1/sum) ----------------
__global__ void __launch_bounds__(256) reduce_kernel(
    const float2* __restrict__ part, float2* __restrict__ stats)
{
    const int wid = threadIdx.x >> 5, lane = threadIdx.x & 31;
    const int row = blockIdx.x * 8 + wid;
    float2 p = part[(size_t)row * 32 + lane];
    float M = p.x;
#pragma unroll
    for (int o = 16; o > 0; o >>= 1) M = fmaxf(M, __shfl_xor_sync(0xffffffffu, M, o));
    float s = p.y * __expf(p.x - M);
#pragma unroll
    for (int o = 16; o > 0; o >>= 1) s += __shfl_xor_sync(0xffffffffu, s, o);
    if (lane == 0) stats[row] = make_float2(M, 1.0f / s);
}

// ---------------- Kernel: PV split-K (single V buffer, 4 blocks/SM) ----------------
__global__ void __launch_bounds__(256, 4) pv_kernel(
    float* __restrict__ attn,
    const u16* __restrict__ Vth, const u16* __restrict__ Vtl,
    const float2* __restrict__ stats,
    float* __restrict__ ctx0, float* __restrict__ ctx1)
{
    extern __shared__ char smem[];
    u32 sb = smem_u32(smem);
    const int tid = threadIdx.x, wid = tid >> 5, lane = tid & 31;
    const int q0 = blockIdx.x * 128;
    const int kseg = blockIdx.y;
    const int bh = blockIdx.z;
    const int kbase = kseg * 16;

    float* smax = (float*)(smem + PV_STATS);
    float* sinv = smax + 128;
    if (tid < 128) {
        float2 st = stats[(size_t)bh * CS + q0 + tid];
        smax[tid] = st.x;
        sinv[tid] = st.y;
    }
    // first V chunk in flight
    cp_tile(sb, PV_VHO, PV_VLO,
            Vth + (size_t)bh * CDK * CS + kbase * 64,
            Vtl + (size_t)bh * CDK * CS + kbase * 64, 64, CS, tid);
    CP_COMMIT();
    __syncthreads();

    const int rb = tid >> 4, cg = (tid & 15) * 4;
    float acc[2][4][4] = {};
    for (int i = 0; i < 16; i++) {
        const int kc = kbase + i;
        // P fill (exp-normalize + split) overlaps the in-flight V copy
#pragma unroll
        for (int p = 0; p < 8; p++) {
            int row = p * 16 + rb;
            size_t ao = ((size_t)(bh * CS + q0 + row)) * CS + kc * 64 + cg;
            float4 rv = __ldcs((const float4*)(attn + ao));
            float mx = smax[row], iv = sinv[row];
            float4 pw;
            pw.x = __expf(rv.x - mx) * iv;
            pw.y = __expf(rv.y - mx) * iv;
            pw.z = __expf(rv.z - mx) * iv;
            pw.w = __expf(rv.w - mx) * iv;
            __stcs((float4*)(attn + ao), pw);
            uint2 hv, lv;
            split_pair(pw.x, pw.y, hv.x, lv.x);
            split_pair(pw.z, pw.w, hv.y, lv.y);
            u32 off = (u32)(row * (LDAB * 2) + cg * 2);
            *(uint2*)(smem + PV_PH + off) = hv;
            *(uint2*)(smem + PV_PL + off) = lv;
        }
        CP_WAIT(0);
        __syncthreads();
        gemm_chunk(sb, PV_PH, PV_PL, PV_VHO, PV_VLO, wid, lane, acc);
        __syncthreads();        // all V reads done before next cp.async overwrites
        if (i < 15) {
            cp_tile(sb, PV_VHO, PV_VLO,
                    Vth + (size_t)bh * CDK * CS + (kc + 1) * 64,
                    Vtl + (size_t)bh * CDK * CS + (kc + 1) * 64, 64, CS, tid);
            CP_COMMIT();
        }
    }

    float* stage = (float*)smem;     // overlaps P region (loop done)
    store_stage(stage, acc, wid, lane);
    __syncthreads();

    float* ctx = kseg ? ctx1 : ctx0;
    const int b = bh / CH, h = bh - b * CH;
    for (int r = wid; r < 128; r += 8) {
        size_t off = ((size_t)(b * CS + q0 + r)) * CD + h * CDK;
        ctx[off + lane]      = stage[r * STAGE_LD + lane];
        ctx[off + 32 + lane] = stage[r * STAGE_LD + 32 + lane];
    }
}

// ---------------- Kernel: output projection (sums split-K partials) ----------------
__global__ void __launch_bounds__(256) outproj_kernel(
    const float* __restrict__ ctx0, const float* __restrict__ ctx1,
    const float* __restrict__ W,
    const float* __restrict__ bias, float* __restrict__ out)
{
    extern __shared__ char smem[];
    u32 sb = smem_u32(smem);
    const int tid = threadIdx.x, wid = tid >> 5, lane = tid & 31;
    const int n0 = blockIdx.x * 64, m0 = blockIdx.y * 128;

    float acc[2][4][4] = {};
    for (int kc = 0; kc < 12; kc++) {
        __syncthreads();
        fill_split2(smem, OFF_AH, OFF_AL,
                    ctx0 + (size_t)m0 * CD + kc * 64,
                    ctx1 + (size_t)m0 * CD + kc * 64, 128, CD, tid);
        fill_split(smem, OFF_BH, OFF_BL, W + (size_t)n0 * CD + kc * 64, 64, CD, tid);
        __syncthreads();
        gemm_chunk(sb, OFF_AH, OFF_AL, OFF_BH, OFF_BL, wid, lane, acc);
    }
    __syncthreads();
    float* stage = (float*)smem;
    store_stage(stage, acc, wid, lane);
    __syncthreads();

    float b0 = bias[n0 + lane];
    float b1 = bias[n0 + 32 + lane];
    for (int r = wid; r < 128; r += 8) {
        size_t off = (size_t)(m0 + r) * CD + n0;
        out[off + lane]      = stage[r * STAGE_LD + lane] + b0;
        out[off + 32 + lane] = stage[r * STAGE_LD + 32 + lane] + b1;
    }
}

// ---------------------------------------------------------------------------
extern "C" void kernel_launch(void* const* d_in, const int* in_sizes, int n_in,
                              void* d_out, int out_size)
{
    (void)in_sizes; (void)n_in; (void)out_size;
    const float* query    = (const float*)d_in[0];
    const float* key      = (const float*)d_in[1];
    const float* value    = (const float*)d_in[2];
    const int*   mask     = (const int*)d_in[3];
    const float* pos_bias = (const float*)d_in[4];
    const float* Wq       = (const float*)d_in[5];
    const float* Wk       = (const float*)d_in[6];
    const float* Wv       = (const float*)d_in[7];
    const float* Wo       = (const float*)d_in[8];
    const float* bo       = (const float*)d_in[9];

    float* out  = (float*)d_out;
    float* attn = out + OUT_ELEMS;

    u16 *pQh, *pQl, *pKh, *pKl, *pVth, *pVtl;
    float *pC0, *pC1;
    float2 *pPart, *pStats;
    cudaGetSymbolAddress((void**)&pQh,  g_Qh);
    cudaGetSymbolAddress((void**)&pQl,  g_Ql);
    cudaGetSymbolAddress((void**)&pKh,  g_Kh);
    cudaGetSymbolAddress((void**)&pKl,  g_Kl);
    cudaGetSymbolAddress((void**)&pVth, g_Vth);
    cudaGetSymbolAddress((void**)&pVtl, g_Vtl);
    cudaGetSymbolAddress((void**)&pC0,  g_ctx0);
    cudaGetSymbolAddress((void**)&pC1,  g_ctx1);
    cudaGetSymbolAddress((void**)&pPart,  g_part);
    cudaGetSymbolAddress((void**)&pStats, g_stats);

    cudaFuncSetAttribute(proj_kernel,    cudaFuncAttributeMaxDynamicSharedMemorySize, PR_SMEM);
    cudaFuncSetAttribute(scores_kernel,  cudaFuncAttributeMaxDynamicSharedMemorySize, PR_SMEM);
    cudaFuncSetAttribute(pv_kernel,      cudaFuncAttributeMaxDynamicSharedMemorySize, PV_SMEM);
    cudaFuncSetAttribute(outproj_kernel, cudaFuncAttributeMaxDynamicSharedMemorySize, PR_SMEM);

    dim3 gProj(CD / 64, CM / 128, 3);          // (12, 32, 3)
    proj_kernel<<<gProj, 256, PR_SMEM>>>(query, key, value, Wq, Wk, Wv,
                                         pQh, pQl, pKh, pKl, pVth, pVtl);

    dim3 gScores(CS / 64, CS / 128, CBH);      // (32, 16, 24), z = h*2+b
    scores_kernel<<<gScores, 256, PR_SMEM>>>(pQh, pQl, pKh, pKl,
                                             pos_bias, mask, attn, pPart);

    reduce_kernel<<<BHS / 8, 256>>>(pPart, pStats);

    dim3 gPV(CS / 128, 2, CBH);                // (16, 2, 24) split-K
    pv_kernel<<<gPV, 256, PV_SMEM>>>(attn, pVth, pVtl, pStats, pC0, pC1);

    dim3 gOut(CD / 64, CM / 128);              // (12, 32)
    outproj_kernel<<<gOut, 256, PR_SMEM>>>(pC0, pC1, Wo, bo, out);
}

// round 16
// speedup vs baseline: 1.2373x; 1.0119x over previous
#include <cuda_runtime.h>
#include <cuda_bf16.h>

#define CB 2
#define CS 2048
#define CD 768
#define CH 12
#define CDK 64
#define CBH 24
#define CM 4096
#define BHS 49152
#define OUT_ELEMS 3145728

typedef unsigned int u32; typedef unsigned short u16;

// bf16 hi/lo pre-split operands
__device__ u16   g_Xh[(size_t)3 * CM * CD];        // query,key,value
__device__ u16   g_Xl[(size_t)3 * CM * CD];
__device__ u16   g_Wh[(size_t)4 * CD * CD];        // Wq,Wk,Wv,Wo
__device__ u16   g_Wl[(size_t)4 * CD * CD];
__device__ u16   g_Qh[(size_t)BHS * CDK];
__device__ u16   g_Ql[(size_t)BHS * CDK];
__device__ u16   g_Kh[(size_t)BHS * CDK];
__device__ u16   g_Kl[(size_t)BHS * CDK];
__device__ u16   g_Vth[(size_t)CBH * CDK * CS];    // [bh][dk][s]
__device__ u16   g_Vtl[(size_t)CBH * CDK * CS];
__device__ float g_ctx0[(size_t)CM * CD];          // split-K partial 0
__device__ float g_ctx1[(size_t)CM * CD];          // split-K partial 1
__device__ float2 g_part[(size_t)BHS * 32];
__device__ float2 g_stats[BHS];

// ---------------- SMEM layouts ----------------
#define LDAB 72                       // bf16 row stride (144 B)
#define STAGE_LD 68                   // fp32 stage stride (16B-aligned rows)
#define OFF_AH 0u
#define OFF_AL 18432u
#define OFF_BH 36864u
#define OFF_BL 46080u
#define PR_SMEM 55296
// pv layout: single V buffer; stage overlaps P region after the loop
#define PV_PH 0u
#define PV_PL 18432u
#define PV_VHO 36864u
#define PV_VLO 46080u
#define PV_STATS 55296u
#define PV_SMEM (55296 + 1024)

// ---------------- helpers ----------------
__device__ __forceinline__ u32 smem_u32(const void* p) {
    u32 a;
    asm("{ .reg .u64 t; cvta.to.shared.u64 t, %1; cvt.u32.u64 %0, t; }" : "=r"(a) : "l"(p));
    return a;
}
__device__ __forceinline__ u32 cvt2(float a, float b) {  // a->low16, b->high16
    u32 r; asm("cvt.rn.bf16x2.f32 %0, %1, %2;" : "=r"(r) : "f"(b), "f"(a)); return r;
}
__device__ __forceinline__ void split_pair(float a, float b, u32& hi, u32& lo) {
    hi = cvt2(a, b);
    float ra = a - __uint_as_float(hi << 16);
    float rb = b - __uint_as_float(hi & 0xffff0000u);
    lo = cvt2(ra, rb);
}
__device__ __forceinline__ void ldm_x4(u32 addr, u32& r0, u32& r1, u32& r2, u32& r3) {
    asm volatile("ldmatrix.sync.aligned.m8n8.x4.shared.b16 {%0,%1,%2,%3}, [%4];"
                 : "=r"(r0), "=r"(r1), "=r"(r2), "=r"(r3) : "r"(addr));
}
__device__ __forceinline__ void mma16816(float* c, const u32* a, u32 b0, u32 b1) {
    asm volatile("mma.sync.aligned.m16n8k16.row.col.f32.bf16.bf16.f32 "
                 "{%0,%1,%2,%3}, {%4,%5,%6,%7}, {%8,%9}, {%0,%1,%2,%3};"
                 : "+f"(c[0]), "+f"(c[1]), "+f"(c[2]), "+f"(c[3])
                 : "r"(a[0]), "r"(a[1]), "r"(a[2]), "r"(a[3]), "r"(b0), "r"(b1));
}
__device__ __forceinline__ void cp16(u32 dst, const void* src) {
    asm volatile("cp.async.cg.shared.global [%0], [%1], 16;" :: "r"(dst), "l"(src));
}
#define CP_COMMIT() asm volatile("cp.async.commit_group;" ::: "memory")
#define CP_WAIT(n)  asm volatile("cp.async.wait_group %0;" :: "n"(n) : "memory")

// fp32 [rows x 64] (row stride rs) -> bf16 hi/lo tiles (padded stride LDAB)
__device__ __forceinline__ void fill_split(char* sp, u32 offH, u32 offL,
        const float* __restrict__ src, int rows, int rs, int tid) {
    const int total = rows * 8;
    for (int idx = tid; idx < total; idx += 256) {
        int r = idx >> 3, c = (idx & 7) * 8;
        const float* p = src + (size_t)r * rs + c;
        float4 v0 = *(const float4*)p;
        float4 v1 = *(const float4*)(p + 4);
        uint4 hv, lv;
        split_pair(v0.x, v0.y, hv.x, lv.x);
        split_pair(v0.z, v0.w, hv.y, lv.y);
        split_pair(v1.x, v1.y, hv.z, lv.z);
        split_pair(v1.z, v1.w, hv.w, lv.w);
        u32 off = (u32)(r * (LDAB * 2) + c * 2);
        *(uint4*)(sp + offH + off) = hv;
        *(uint4*)(sp + offL + off) = lv;
    }
}

// sum of two fp32 sources -> bf16 hi/lo tiles
__device__ __forceinline__ void fill_split2(char* sp, u32 offH, u32 offL,
        const float* __restrict__ s0, const float* __restrict__ s1,
        int rows, int rs, int tid) {
    const int total = rows * 8;
    for (int idx = tid; idx < total; idx += 256) {
        int r = idx >> 3, c = (idx & 7) * 8;
        const float* pa = s0 + (size_t)r * rs + c;
        const float* pb = s1 + (size_t)r * rs + c;
        float4 a0 = *(const float4*)pa;
        float4 a1 = *(const float4*)(pa + 4);
        float4 b0 = *(const float4*)pb;
        float4 b1 = *(const float4*)(pb + 4);
        a0.x += b0.x; a0.y += b0.y; a0.z += b0.z; a0.w += b0.w;
        a1.x += b1.x; a1.y += b1.y; a1.z += b1.z; a1.w += b1.w;
        uint4 hv, lv;
        split_pair(a0.x, a0.y, hv.x, lv.x);
        split_pair(a0.z, a0.w, hv.y, lv.y);
        split_pair(a1.x, a1.y, hv.z, lv.z);
        split_pair(a1.z, a1.w, hv.w, lv.w);
        u32 off = (u32)(r * (LDAB * 2) + c * 2);
        *(uint4*)(sp + offH + off) = hv;
        *(uint4*)(sp + offL + off) = lv;
    }
}

// cp.async a [rows x 64] bf16 tile pair (hi/lo, row stride rsu16)
__device__ __forceinline__ void cp_tile(u32 sb, u32 offH, u32 offL,
        const u16* __restrict__ srcH, const u16* __restrict__ srcL,
        int rows, int rsu16, int tid) {
    const int per = rows * 8;
    for (int idx = tid; idx < per * 2; idx += 256) {
        int half = idx >= per, rem = half ? idx - per : idx;
        int r = rem >> 3, c = rem & 7;
        const u16* s = (half ? srcL : srcH) + (size_t)r * rsu16 + c * 8;
        cp16(sb + (half ? offL : offH) + (u32)(r * (LDAB * 2) + c * 16), s);
    }
}

// one 64-deep k-chunk of the 128x64 block tile, bf16x3 (hh + hl + lh)
__device__ __forceinline__ void gemm_chunk(u32 sb, u32 offAH, u32 offAL,
        u32 offBH, u32 offBL, int wid, int lane, float (*acc)[4][4]) {
    const int MW = (wid >> 1) * 32, NW = (wid & 1) * 32;
    const u32 aRow = lane & 15;
    const u32 aCol = (lane >> 4) * 8;
    const u32 bRow = ((lane >> 4) << 3) + (lane & 7);
    const u32 bCol = ((lane >> 3) & 1) * 8;
#pragma unroll
    for (int ks = 0; ks < 4; ks++) {
        const u32 kb = ks * 16;
        u32 ah[2][4], al[2][4], bh[2][4], bl[2][4];
#pragma unroll
        for (int t = 0; t < 2; t++) {
            u32 ro = (MW + 16 * t + aRow) * (LDAB * 2) + (kb + aCol) * 2;
            ldm_x4(sb + offAH + ro, ah[t][0], ah[t][1], ah[t][2], ah[t][3]);
            ldm_x4(sb + offAL + ro, al[t][0], al[t][1], al[t][2], al[t][3]);
        }
#pragma unroll
        for (int g = 0; g < 2; g++) {
            u32 ro = (NW + 16 * g + bRow) * (LDAB * 2) + (kb + bCol) * 2;
            ldm_x4(sb + offBH + ro, bh[g][0], bh[g][1], bh[g][2], bh[g][3]);
            ldm_x4(sb + offBL + ro, bl[g][0], bl[g][1], bl[g][2], bl[g][3]);
        }
#pragma unroll
        for (int t = 0; t < 2; t++)
#pragma unroll
            for (int u = 0; u < 4; u++) {
                const int g = u >> 1, pr = (u & 1) * 2;
                mma16816(acc[t][u], ah[t], bh[g][pr], bh[g][pr + 1]);
                mma16816(acc[t][u], ah[t], bl[g][pr], bl[g][pr + 1]);
                mma16816(acc[t][u], al[t], bh[g][pr], bh[g][pr + 1]);
            }
    }
}

__device__ __forceinline__ void store_stage(float* stage, float (*acc)[4][4], int wid, int lane) {
    const int MW = (wid >> 1) * 32, NW = (wid & 1) * 32;
    const int r0 = lane >> 2, c0 = (lane & 3) * 2;
#pragma unroll
    for (int t = 0; t < 2; t++)
#pragma unroll
        for (int u = 0; u < 4; u++) {
            float* p0 = stage + (MW + 16 * t + r0) * STAGE_LD + NW + 8 * u + c0;
            p0[0] = acc[t][u][0];
            p0[1] = acc[t][u][1];
            float* p1 = p0 + 8 * STAGE_LD;
            p1[0] = acc[t][u][2];
            p1[1] = acc[t][u][3];
        }
}

// ---------------- Kernel: elementwise fp32 -> bf16 hi/lo split ----------------
// z selects one of nT same-size tensors laid out consecutively in dst.
__global__ void __launch_bounds__(256) splitx_kernel(
    const float* __restrict__ s0, const float* __restrict__ s1, const float* __restrict__ s2,
    u16* __restrict__ dh, u16* __restrict__ dl, int n4)
{
    const int z = blockIdx.y;
    const float* src = (z == 0) ? s0 : (z == 1) ? s1 : s2;
    int i = blockIdx.x * 256 + threadIdx.x;
    if (i >= n4) return;
    float4 v = ((const float4*)src)[i];
    uint2 hv, lv;
    split_pair(v.x, v.y, hv.x, lv.x);
    split_pair(v.z, v.w, hv.y, lv.y);
    size_t o = (size_t)z * n4 + i;
    ((uint2*)dh)[o] = hv;
    ((uint2*)dl)[o] = lv;
}
__global__ void __launch_bounds__(256) splitw_kernel(
    const float* __restrict__ s0, const float* __restrict__ s1,
    const float* __restrict__ s2, const float* __restrict__ s3,
    u16* __restrict__ dh, u16* __restrict__ dl, int n4)
{
    const int z = blockIdx.y;
    const float* src = (z == 0) ? s0 : (z == 1) ? s1 : (z == 2) ? s2 : s3;
    int i = blockIdx.x * 256 + threadIdx.x;
    if (i >= n4) return;
    float4 v = ((const float4*)src)[i];
    uint2 hv, lv;
    split_pair(v.x, v.y, hv.x, lv.x);
    split_pair(v.z, v.w, hv.y, lv.y);
    size_t o = (size_t)z * n4 + i;
    ((uint2*)dh)[o] = hv;
    ((uint2*)dl)[o] = lv;
}

// ---------------- Kernel: merged QKV projection (pre-split inputs, cp.async) ----------------
__global__ void __launch_bounds__(256, 4) proj_kernel(
    const u16* __restrict__ Xh, const u16* __restrict__ Xl,
    const u16* __restrict__ Wh, const u16* __restrict__ Wl,
    u16* __restrict__ Qh, u16* __restrict__ Ql,
    u16* __restrict__ Kh, u16* __restrict__ Kl,
    u16* __restrict__ Vth, u16* __restrict__ Vtl)
{
    extern __shared__ char smem[];
    u32 sb = smem_u32(smem);
    const int tid = threadIdx.x, wid = tid >> 5, lane = tid & 31;
    const int n0 = blockIdx.x * 64, m0 = blockIdx.y * 128;
    const int z = blockIdx.z;

    const u16* xh = Xh + (size_t)z * CM * CD + (size_t)m0 * CD;
    const u16* xl = Xl + (size_t)z * CM * CD + (size_t)m0 * CD;
    const u16* wh = Wh + (size_t)z * CD * CD + (size_t)n0 * CD;
    const u16* wl = Wl + (size_t)z * CD * CD + (size_t)n0 * CD;

    float acc[2][4][4] = {};
    for (int kc = 0; kc < 12; kc++) {
        cp_tile(sb, OFF_AH, OFF_AL, xh + kc * 64, xl + kc * 64, 128, CD, tid);
        cp_tile(sb, OFF_BH, OFF_BL, wh + kc * 64, wl + kc * 64, 64, CD, tid);
        CP_COMMIT();
        CP_WAIT(0);
        __syncthreads();
        gemm_chunk(sb, OFF_AH, OFF_AL, OFF_BH, OFF_BL, wid, lane, acc);
        __syncthreads();
    }
    float* stage = (float*)smem;
    store_stage(stage, acc, wid, lane);
    __syncthreads();

    const int b = m0 >> 11, s0 = m0 & (CS - 1), h = n0 >> 6;
    if (z < 2) {
        u16* Oh = (z == 0) ? Qh : Kh;
        u16* Ol = (z == 0) ? Ql : Kl;
        for (int r = wid; r < 128; r += 8) {
            float c0 = stage[r * STAGE_LD + 2 * lane];
            float c1 = stage[r * STAGE_LD + 2 * lane + 1];
            u32 hv, lv;
            split_pair(c0, c1, hv, lv);
            size_t off32 = ((size_t)((b * CH + h) * CS + s0 + r)) * 32;
            ((u32*)Oh)[off32 + lane] = hv;
            ((u32*)Ol)[off32 + lane] = lv;
        }
    } else {
        for (int c = wid; c < 64; c += 8) {
            size_t off32 = ((size_t)((b * CH + h) * CDK + c)) * (CS / 2) + s0 / 2;
#pragma unroll
            for (int j = 0; j < 2; j++) {
                int p = lane + 32 * j;
                float s0v = stage[(2 * p) * STAGE_LD + c];
                float s1v = stage[(2 * p + 1) * STAGE_LD + c];
                u32 hv, lv;
                split_pair(s0v, s1v, hv, lv);
                ((u32*)Vth)[off32 + p] = hv;
                ((u32*)Vtl)[off32 + p] = lv;
            }
        }
    }
}

// ---------------- Kernel: scores (z = h*2+b), 4 blocks/SM ----------------
__global__ void __launch_bounds__(256, 4) scores_kernel(
    const u16* __restrict__ Qh, const u16* __restrict__ Ql,
    const u16* __restrict__ Kh, const u16* __restrict__ Kl,
    const float* __restrict__ pos_bias, const int* __restrict__ mask,
    float* __restrict__ raw, float2* __restrict__ part)
{
    extern __shared__ char smem[];
    u32 sb = smem_u32(smem);
    const int tid = threadIdx.x, wid = tid >> 5, lane = tid & 31;
    const int kx = blockIdx.x, kk0 = kx * 64;
    const int q0 = blockIdx.y * 128;
    const int h = blockIdx.z >> 1, b = blockIdx.z & 1;
    const int bh = b * CH + h;

    cp_tile(sb, OFF_AH, OFF_AL,
            Qh + ((size_t)bh * CS + q0) * CDK,
            Ql + ((size_t)bh * CS + q0) * CDK, 128, CDK, tid);
    cp_tile(sb, OFF_BH, OFF_BL,
            Kh + ((size_t)bh * CS + kk0) * CDK,
            Kl + ((size_t)bh * CS + kk0) * CDK, 64, CDK, tid);
    CP_COMMIT();
    CP_WAIT(0);
    __syncthreads();

    float acc[2][4][4] = {};
    gemm_chunk(sb, OFF_AH, OFF_AL, OFF_BH, OFF_BL, wid, lane, acc);
    __syncthreads();
    float* stage = (float*)smem;
    store_stage(stage, acc, wid, lane);
    __syncthreads();

    const int halfl = lane >> 4;
    const int cq = (lane & 15) * 4;
#pragma unroll
    for (int it = 0; it < 8; it++) {
        const int r = wid * 16 + it * 2 + halfl;
        const int q = q0 + r;
        float4 pb = *(const float4*)(pos_bias + ((size_t)(h * CS + q)) * CS + kk0 + cq);
        int4   mk = *(const int4*)(mask + ((size_t)(b * CS + q)) * CS + kk0 + cq);
        float4 sv = *(const float4*)(stage + r * STAGE_LD + cq);
        float4 rv;
        rv.x = (mk.x == 0) ? -1e9f : sv.x * 0.125f + pb.x;
        rv.y = (mk.y == 0) ? -1e9f : sv.y * 0.125f + pb.y;
        rv.z = (mk.z == 0) ? -1e9f : sv.z * 0.125f + pb.z;
        rv.w = (mk.w == 0) ? -1e9f : sv.w * 0.125f + pb.w;
        __stcs((float4*)(raw + ((size_t)(bh * CS + q)) * CS + kk0 + cq), rv);

        float mx = fmaxf(fmaxf(rv.x, rv.y), fmaxf(rv.z, rv.w));
#pragma unroll
        for (int o = 8; o > 0; o >>= 1) mx = fmaxf(mx, __shfl_xor_sync(0xffffffffu, mx, o));
        float se = __expf(rv.x - mx) + __expf(rv.y - mx) +
                   __expf(rv.z - mx) + __expf(rv.w - mx);
#pragma unroll
        for (int o = 8; o > 0; o >>= 1) se += __shfl_xor_sync(0xffffffffu, se, o);
        if ((lane & 15) == 0)
            part[((size_t)(bh * CS + q)) * 32 + kx] = make_float2(mx, se);
    }
}

// ---------------- Kernel: reduce partials -> (max, 1/sum) ----------------
__global__ void __launch_bounds__(256) reduce_kernel(
    const float2* __restrict__ part, float2* __restrict__ stats)
{
    const int wid = threadIdx.x >> 5, lane = threadIdx.x & 31;
    const int row = blockIdx.x * 8 + wid;
    float2 p = part[(size_t)row * 32 + lane];
    float M = p.x;
#pragma unroll
    for (int o = 16; o > 0; o >>= 1) M = fmaxf(M, __shfl_xor_sync(0xffffffffu, M, o));
    float s = p.y * __expf(p.x - M);
#pragma unroll
    for (int o = 16; o > 0; o >>= 1) s += __shfl_xor_sync(0xffffffffu, s, o);
    if (lane == 0) stats[row] = make_float2(M, 1.0f / s);
}

// ---------------- Kernel: PV split-K (single V buffer, 4 blocks/SM) ----------------
__global__ void __launch_bounds__(256, 4) pv_kernel(
    float* __restrict__ attn,
    const u16* __restrict__ Vth, const u16* __restrict__ Vtl,
    const float2* __restrict__ stats,
    float* __restrict__ ctx0, float* __restrict__ ctx1)
{
    extern __shared__ char smem[];
    u32 sb = smem_u32(smem);
    const int tid = threadIdx.x, wid = tid >> 5, lane = tid & 31;
    const int q0 = blockIdx.x * 128;
    const int kseg = blockIdx.y;
    const int bh = blockIdx.z;
    const int kbase = kseg * 16;

    float* smax = (float*)(smem + PV_STATS);
    float* sinv = smax + 128;
    if (tid < 128) {
        float2 st = stats[(size_t)bh * CS + q0 + tid];
        smax[tid] = st.x;
        sinv[tid] = st.y;
    }
    cp_tile(sb, PV_VHO, PV_VLO,
            Vth + (size_t)bh * CDK * CS + kbase * 64,
            Vtl + (size_t)bh * CDK * CS + kbase * 64, 64, CS, tid);
    CP_COMMIT();
    __syncthreads();

    const int rb = tid >> 4, cg = (tid & 15) * 4;
    float acc[2][4][4] = {};
    for (int i = 0; i < 16; i++) {
        const int kc = kbase + i;
#pragma unroll
        for (int p = 0; p < 8; p++) {
            int row = p * 16 + rb;
            size_t ao = ((size_t)(bh * CS + q0 + row)) * CS + kc * 64 + cg;
            float4 rv = __ldcs((const float4*)(attn + ao));
            float mx = smax[row], iv = sinv[row];
            float4 pw;
            pw.x = __expf(rv.x - mx) * iv;
            pw.y = __expf(rv.y - mx) * iv;
            pw.z = __expf(rv.z - mx) * iv;
            pw.w = __expf(rv.w - mx) * iv;
            __stcs((float4*)(attn + ao), pw);
            uint2 hv, lv;
            split_pair(pw.x, pw.y, hv.x, lv.x);
            split_pair(pw.z, pw.w, hv.y, lv.y);
            u32 off = (u32)(row * (LDAB * 2) + cg * 2);
            *(uint2*)(smem + PV_PH + off) = hv;
            *(uint2*)(smem + PV_PL + off) = lv;
        }
        CP_WAIT(0);
        __syncthreads();
        gemm_chunk(sb, PV_PH, PV_PL, PV_VHO, PV_VLO, wid, lane, acc);
        __syncthreads();
        if (i < 15) {
            cp_tile(sb, PV_VHO, PV_VLO,
                    Vth + (size_t)bh * CDK * CS + (kc + 1) * 64,
                    Vtl + (size_t)bh * CDK * CS + (kc + 1) * 64, 64, CS, tid);
            CP_COMMIT();
        }
    }

    float* stage = (float*)smem;
    store_stage(stage, acc, wid, lane);
    __syncthreads();

    float* ctx = kseg ? ctx1 : ctx0;
    const int b = bh / CH, h = bh - b * CH;
    for (int r = wid; r < 128; r += 8) {
        size_t off = ((size_t)(b * CS + q0 + r)) * CD + h * CDK;
        ctx[off + lane]      = stage[r * STAGE_LD + lane];
        ctx[off + 32 + lane] = stage[r * STAGE_LD + 32 + lane];
    }
}

// ---------------- Kernel: output projection (pre-split Wo via cp.async) ----------------
__global__ void __launch_bounds__(256) outproj_kernel(
    const float* __restrict__ ctx0, const float* __restrict__ ctx1,
    const u16* __restrict__ Wh, const u16* __restrict__ Wl,
    const float* __restrict__ bias, float* __restrict__ out)
{
    extern __shared__ char smem[];
    u32 sb = smem_u32(smem);
    const int tid = threadIdx.x, wid = tid >> 5, lane = tid & 31;
    const int n0 = blockIdx.x * 64, m0 = blockIdx.y * 128;

    const u16* wh = Wh + (size_t)3 * CD * CD + (size_t)n0 * CD;
    const u16* wl = Wl + (size_t)3 * CD * CD + (size_t)n0 * CD;

    float acc[2][4][4] = {};
    for (int kc = 0; kc < 12; kc++) {
        cp_tile(sb, OFF_BH, OFF_BL, wh + kc * 64, wl + kc * 64, 64, CD, tid);
        CP_COMMIT();
        fill_split2(smem, OFF_AH, OFF_AL,
                    ctx0 + (size_t)m0 * CD + kc * 64,
                    ctx1 + (size_t)m0 * CD + kc * 64, 128, CD, tid);
        CP_WAIT(0);
        __syncthreads();
        gemm_chunk(sb, OFF_AH, OFF_AL, OFF_BH, OFF_BL, wid, lane, acc);
        __syncthreads();
    }
    float* stage = (float*)smem;
    store_stage(stage, acc, wid, lane);
    __syncthreads();

    float b0 = bias[n0 + lane];
    float b1 = bias[n0 + 32 + lane];
    for (int r = wid; r < 128; r += 8) {
        size_t off = (size_t)(m0 + r) * CD + n0;
        out[off + lane]      = stage[r * STAGE_LD + lane] + b0;
        out[off + 32 + lane] = stage[r * STAGE_LD + 32 + lane] + b1;
    }
}

// ---------------------------------------------------------------------------
extern "C" void kernel_launch(void* const* d_in, const int* in_sizes, int n_in,
                              void* d_out, int out_size)
{
    (void)in_sizes; (void)n_in; (void)out_size;
    const float* query    = (const float*)d_in[0];
    const float* key      = (const float*)d_in[1];
    const float* value    = (const float*)d_in[2];
    const int*   mask     = (const int*)d_in[3];
    const float* pos_bias = (const float*)d_in[4];
    const float* Wq       = (const float*)d_in[5];
    const float* Wk       = (const float*)d_in[6];
    const float* Wv       = (const float*)d_in[7];
    const float* Wo       = (const float*)d_in[8];
    const float* bo       = (const float*)d_in[9];

    float* out  = (float*)d_out;
    float* attn = out + OUT_ELEMS;

    u16 *pXh, *pXl, *pWh, *pWl, *pQh, *pQl, *pKh, *pKl, *pVth, *pVtl;
    float *pC0, *pC1;
    float2 *pPart, *pStats;
    cudaGetSymbolAddress((void**)&pXh,  g_Xh);
    cudaGetSymbolAddress((void**)&pXl,  g_Xl);
    cudaGetSymbolAddress((void**)&pWh,  g_Wh);
    cudaGetSymbolAddress((void**)&pWl,  g_Wl);
    cudaGetSymbolAddress((void**)&pQh,  g_Qh);
    cudaGetSymbolAddress((void**)&pQl,  g_Ql);
    cudaGetSymbolAddress((void**)&pKh,  g_Kh);
    cudaGetSymbolAddress((void**)&pKl,  g_Kl);
    cudaGetSymbolAddress((void**)&pVth, g_Vth);
    cudaGetSymbolAddress((void**)&pVtl, g_Vtl);
    cudaGetSymbolAddress((void**)&pC0,  g_ctx0);
    cudaGetSymbolAddress((void**)&pC1,  g_ctx1);
    cudaGetSymbolAddress((void**)&pPart,  g_part);
    cudaGetSymbolAddress((void**)&pStats, g_stats);

    cudaFuncSetAttribute(proj_kernel,    cudaFuncAttributeMaxDynamicSharedMemorySize, PR_SMEM);
    cudaFuncSetAttribute(scores_kernel,  cudaFuncAttributeMaxDynamicSharedMemorySize, PR_SMEM);
    cudaFuncSetAttribute(pv_kernel,      cudaFuncAttributeMaxDynamicSharedMemorySize, PV_SMEM);
    cudaFuncSetAttribute(outproj_kernel, cudaFuncAttributeMaxDynamicSharedMemorySize, PR_SMEM);

    // pre-split inputs and weights to bf16 hi/lo
    const int nX4 = CM * CD / 4;   // 786432
    const int nW4 = CD * CD / 4;   // 147456
    dim3 gSX((nX4 + 255) / 256, 3);
    splitx_kernel<<<gSX, 256>>>(query, key, value, pXh, pXl, nX4);
    dim3 gSW((nW4 + 255) / 256, 4);
    splitw_kernel<<<gSW, 256>>>(Wq, Wk, Wv, Wo, pWh, pWl, nW4);

    dim3 gProj(CD / 64, CM / 128, 3);          // (12, 32, 3)
    proj_kernel<<<gProj, 256, PR_SMEM>>>(pXh, pXl, pWh, pWl,
                                         pQh, pQl, pKh, pKl, pVth, pVtl);

    dim3 gScores(CS / 64, CS / 128, CBH);      // (32, 16, 24), z = h*2+b
    scores_kernel<<<gScores, 256, PR_SMEM>>>(pQh, pQl, pKh, pKl,
                                             pos_bias, mask, attn, pPart);

    reduce_kernel<<<BHS / 8, 256>>>(pPart, pStats);

    dim3 gPV(CS / 128, 2, CBH);                // (16, 2, 24) split-K
    pv_kernel<<<gPV, 256, PV_SMEM>>>(attn, pVth, pVtl, pStats, pC0, pC1);

    dim3 gOut(CD / 64, CM / 128);              // (12, 32)
    outproj_kernel<<<gOut, 256, PR_SMEM>>>(pC0, pC1, pWh, pWl, bo, out);
}

// round 17
// speedup vs baseline: 1.2553x; 1.0146x over previous
#include <cuda_runtime.h>
#include <cuda_bf16.h>

#define CB 2
#define CS 2048
#define CD 768
#define CH 12
#define CDK 64
#define CBH 24
#define CM 4096
#define BHS 49152
#define OUT_ELEMS 3145728

typedef unsigned int u32; typedef unsigned short u16; typedef unsigned char u8;

// bf16 hi/lo pre-split operands
__device__ u16   g_Xh[(size_t)3 * CM * CD];        // query,key,value
__device__ u16   g_Xl[(size_t)3 * CM * CD];
__device__ u16   g_Wh[(size_t)4 * CD * CD];        // Wq,Wk,Wv,Wo
__device__ u16   g_Wl[(size_t)4 * CD * CD];
__device__ u16   g_Qh[(size_t)BHS * CDK];
__device__ u16   g_Ql[(size_t)BHS * CDK];
__device__ u16   g_Kh[(size_t)BHS * CDK];
__device__ u16   g_Kl[(size_t)BHS * CDK];
__device__ u16   g_Vth[(size_t)CBH * CDK * CS];    // [bh][dk][s]
__device__ u16   g_Vtl[(size_t)CBH * CDK * CS];
__device__ u8    g_mask8[(size_t)CB * CS * CS];    // mask as u8
__device__ float g_ctx0[(size_t)CM * CD];          // split-K partial 0
__device__ float g_ctx1[(size_t)CM * CD];          // split-K partial 1
__device__ float2 g_part[(size_t)BHS * 32];
__device__ float2 g_stats[BHS];

// ---------------- SMEM layouts ----------------
#define LDAB 72                       // bf16 row stride (144 B)
#define STAGE_LD 68                   // fp32 stage stride (16B-aligned rows)
#define OFF_AH 0u
#define OFF_AL 18432u
#define OFF_BH 36864u
#define OFF_BL 46080u
#define PR_SMEM 55296
// pv layout: single V buffer; stage overlaps P region after the loop
#define PV_PH 0u
#define PV_PL 18432u
#define PV_VHO 36864u
#define PV_VLO 46080u
#define PV_STATS 55296u
#define PV_SMEM (55296 + 1024)

// ---------------- helpers ----------------
__device__ __forceinline__ u32 smem_u32(const void* p) {
    u32 a;
    asm("{ .reg .u64 t; cvta.to.shared.u64 t, %1; cvt.u32.u64 %0, t; }" : "=r"(a) : "l"(p));
    return a;
}
__device__ __forceinline__ u32 cvt2(float a, float b) {  // a->low16, b->high16
    u32 r; asm("cvt.rn.bf16x2.f32 %0, %1, %2;" : "=r"(r) : "f"(b), "f"(a)); return r;
}
__device__ __forceinline__ void split_pair(float a, float b, u32& hi, u32& lo) {
    hi = cvt2(a, b);
    float ra = a - __uint_as_float(hi << 16);
    float rb = b - __uint_as_float(hi & 0xffff0000u);
    lo = cvt2(ra, rb);
}
__device__ __forceinline__ void ldm_x4(u32 addr, u32& r0, u32& r1, u32& r2, u32& r3) {
    asm volatile("ldmatrix.sync.aligned.m8n8.x4.shared.b16 {%0,%1,%2,%3}, [%4];"
                 : "=r"(r0), "=r"(r1), "=r"(r2), "=r"(r3) : "r"(addr));
}
__device__ __forceinline__ void mma16816(float* c, const u32* a, u32 b0, u32 b1) {
    asm volatile("mma.sync.aligned.m16n8k16.row.col.f32.bf16.bf16.f32 "
                 "{%0,%1,%2,%3}, {%4,%5,%6,%7}, {%8,%9}, {%0,%1,%2,%3};"
                 : "+f"(c[0]), "+f"(c[1]), "+f"(c[2]), "+f"(c[3])
                 : "r"(a[0]), "r"(a[1]), "r"(a[2]), "r"(a[3]), "r"(b0), "r"(b1));
}
__device__ __forceinline__ void cp16(u32 dst, const void* src) {
    asm volatile("cp.async.cg.shared.global [%0], [%1], 16;" :: "r"(dst), "l"(src));
}
#define CP_COMMIT() asm volatile("cp.async.commit_group;" ::: "memory")
#define CP_WAIT(n)  asm volatile("cp.async.wait_group %0;" :: "n"(n) : "memory")

// sum of two fp32 sources -> bf16 hi/lo tiles
__device__ __forceinline__ void fill_split2(char* sp, u32 offH, u32 offL,
        const float* __restrict__ s0, const float* __restrict__ s1,
        int rows, int rs, int tid) {
    const int total = rows * 8;
    for (int idx = tid; idx < total; idx += 256) {
        int r = idx >> 3, c = (idx & 7) * 8;
        const float* pa = s0 + (size_t)r * rs + c;
        const float* pb = s1 + (size_t)r * rs + c;
        float4 a0 = *(const float4*)pa;
        float4 a1 = *(const float4*)(pa + 4);
        float4 b0 = *(const float4*)pb;
        float4 b1 = *(const float4*)(pb + 4);
        a0.x += b0.x; a0.y += b0.y; a0.z += b0.z; a0.w += b0.w;
        a1.x += b1.x; a1.y += b1.y; a1.z += b1.z; a1.w += b1.w;
        uint4 hv, lv;
        split_pair(a0.x, a0.y, hv.x, lv.x);
        split_pair(a0.z, a0.w, hv.y, lv.y);
        split_pair(a1.x, a1.y, hv.z, lv.z);
        split_pair(a1.z, a1.w, hv.w, lv.w);
        u32 off = (u32)(r * (LDAB * 2) + c * 2);
        *(uint4*)(sp + offH + off) = hv;
        *(uint4*)(sp + offL + off) = lv;
    }
}

// cp.async a [rows x 64] bf16 tile pair (hi/lo, row stride rsu16)
__device__ __forceinline__ void cp_tile(u32 sb, u32 offH, u32 offL,
        const u16* __restrict__ srcH, const u16* __restrict__ srcL,
        int rows, int rsu16, int tid) {
    const int per = rows * 8;
    for (int idx = tid; idx < per * 2; idx += 256) {
        int half = idx >= per, rem = half ? idx - per : idx;
        int r = rem >> 3, c = rem & 7;
        const u16* s = (half ? srcL : srcH) + (size_t)r * rsu16 + c * 8;
        cp16(sb + (half ? offL : offH) + (u32)(r * (LDAB * 2) + c * 16), s);
    }
}

// one 64-deep k-chunk of the 128x64 block tile, bf16x3 (hh + hl + lh)
__device__ __forceinline__ void gemm_chunk(u32 sb, u32 offAH, u32 offAL,
        u32 offBH, u32 offBL, int wid, int lane, float (*acc)[4][4]) {
    const int MW = (wid >> 1) * 32, NW = (wid & 1) * 32;
    const u32 aRow = lane & 15;
    const u32 aCol = (lane >> 4) * 8;
    const u32 bRow = ((lane >> 4) << 3) + (lane & 7);
    const u32 bCol = ((lane >> 3) & 1) * 8;
#pragma unroll
    for (int ks = 0; ks < 4; ks++) {
        const u32 kb = ks * 16;
        u32 ah[2][4], al[2][4], bh[2][4], bl[2][4];
#pragma unroll
        for (int t = 0; t < 2; t++) {
            u32 ro = (MW + 16 * t + aRow) * (LDAB * 2) + (kb + aCol) * 2;
            ldm_x4(sb + offAH + ro, ah[t][0], ah[t][1], ah[t][2], ah[t][3]);
            ldm_x4(sb + offAL + ro, al[t][0], al[t][1], al[t][2], al[t][3]);
        }
#pragma unroll
        for (int g = 0; g < 2; g++) {
            u32 ro = (NW + 16 * g + bRow) * (LDAB * 2) + (kb + bCol) * 2;
            ldm_x4(sb + offBH + ro, bh[g][0], bh[g][1], bh[g][2], bh[g][3]);
            ldm_x4(sb + offBL + ro, bl[g][0], bl[g][1], bl[g][2], bl[g][3]);
        }
#pragma unroll
        for (int t = 0; t < 2; t++)
#pragma unroll
            for (int u = 0; u < 4; u++) {
                const int g = u >> 1, pr = (u & 1) * 2;
                mma16816(acc[t][u], ah[t], bh[g][pr], bh[g][pr + 1]);
                mma16816(acc[t][u], ah[t], bl[g][pr], bl[g][pr + 1]);
                mma16816(acc[t][u], al[t], bh[g][pr], bh[g][pr + 1]);
            }
    }
}

__device__ __forceinline__ void store_stage(float* stage, float (*acc)[4][4], int wid, int lane) {
    const int MW = (wid >> 1) * 32, NW = (wid & 1) * 32;
    const int r0 = lane >> 2, c0 = (lane & 3) * 2;
#pragma unroll
    for (int t = 0; t < 2; t++)
#pragma unroll
        for (int u = 0; u < 4; u++) {
            float* p0 = stage + (MW + 16 * t + r0) * STAGE_LD + NW + 8 * u + c0;
            p0[0] = acc[t][u][0];
            p0[1] = acc[t][u][1];
            float* p1 = p0 + 8 * STAGE_LD;
            p1[0] = acc[t][u][2];
            p1[1] = acc[t][u][3];
        }
}

// ---------------- Kernel: elementwise fp32 -> bf16 hi/lo split ----------------
__global__ void __launch_bounds__(256) splitx_kernel(
    const float* __restrict__ s0, const float* __restrict__ s1, const float* __restrict__ s2,
    u16* __restrict__ dh, u16* __restrict__ dl, int n4)
{
    const int z = blockIdx.y;
    const float* src = (z == 0) ? s0 : (z == 1) ? s1 : s2;
    int i = blockIdx.x * 256 + threadIdx.x;
    if (i >= n4) return;
    float4 v = ((const float4*)src)[i];
    uint2 hv, lv;
    split_pair(v.x, v.y, hv.x, lv.x);
    split_pair(v.z, v.w, hv.y, lv.y);
    size_t o = (size_t)z * n4 + i;
    ((uint2*)dh)[o] = hv;
    ((uint2*)dl)[o] = lv;
}
__global__ void __launch_bounds__(256) splitw_kernel(
    const float* __restrict__ s0, const float* __restrict__ s1,
    const float* __restrict__ s2, const float* __restrict__ s3,
    u16* __restrict__ dh, u16* __restrict__ dl, int n4)
{
    const int z = blockIdx.y;
    const float* src = (z == 0) ? s0 : (z == 1) ? s1 : (z == 2) ? s2 : s3;
    int i = blockIdx.x * 256 + threadIdx.x;
    if (i >= n4) return;
    float4 v = ((const float4*)src)[i];
    uint2 hv, lv;
    split_pair(v.x, v.y, hv.x, lv.x);
    split_pair(v.z, v.w, hv.y, lv.y);
    size_t o = (size_t)z * n4 + i;
    ((uint2*)dh)[o] = hv;
    ((uint2*)dl)[o] = lv;
}

// ---------------- Kernel: mask int32 -> u8 ----------------
__global__ void __launch_bounds__(256) mask8_kernel(
    const int* __restrict__ mask, u8* __restrict__ m8, int n4)
{
    int i = blockIdx.x * 256 + threadIdx.x;
    if (i >= n4) return;
    int4 v = ((const int4*)mask)[i];
    uchar4 o;
    o.x = (u8)v.x; o.y = (u8)v.y; o.z = (u8)v.z; o.w = (u8)v.w;
    ((uchar4*)m8)[i] = o;
}

// ---------------- Kernel: merged QKV projection (pre-split inputs, cp.async) ----------------
__global__ void __launch_bounds__(256, 4) proj_kernel(
    const u16* __restrict__ Xh, const u16* __restrict__ Xl,
    const u16* __restrict__ Wh, const u16* __restrict__ Wl,
    u16* __restrict__ Qh, u16* __restrict__ Ql,
    u16* __restrict__ Kh, u16* __restrict__ Kl,
    u16* __restrict__ Vth, u16* __restrict__ Vtl)
{
    extern __shared__ char smem[];
    u32 sb = smem_u32(smem);
    const int tid = threadIdx.x, wid = tid >> 5, lane = tid & 31;
    const int n0 = blockIdx.x * 64, m0 = blockIdx.y * 128;
    const int z = blockIdx.z;

    const u16* xh = Xh + (size_t)z * CM * CD + (size_t)m0 * CD;
    const u16* xl = Xl + (size_t)z * CM * CD + (size_t)m0 * CD;
    const u16* wh = Wh + (size_t)z * CD * CD + (size_t)n0 * CD;
    const u16* wl = Wl + (size_t)z * CD * CD + (size_t)n0 * CD;

    float acc[2][4][4] = {};
    for (int kc = 0; kc < 12; kc++) {
        cp_tile(sb, OFF_AH, OFF_AL, xh + kc * 64, xl + kc * 64, 128, CD, tid);
        cp_tile(sb, OFF_BH, OFF_BL, wh + kc * 64, wl + kc * 64, 64, CD, tid);
        CP_COMMIT();
        CP_WAIT(0);
        __syncthreads();
        gemm_chunk(sb, OFF_AH, OFF_AL, OFF_BH, OFF_BL, wid, lane, acc);
        __syncthreads();
    }
    float* stage = (float*)smem;
    store_stage(stage, acc, wid, lane);
    __syncthreads();

    const int b = m0 >> 11, s0 = m0 & (CS - 1), h = n0 >> 6;
    if (z < 2) {
        u16* Oh = (z == 0) ? Qh : Kh;
        u16* Ol = (z == 0) ? Ql : Kl;
        for (int r = wid; r < 128; r += 8) {
            float c0 = stage[r * STAGE_LD + 2 * lane];
            float c1 = stage[r * STAGE_LD + 2 * lane + 1];
            u32 hv, lv;
            split_pair(c0, c1, hv, lv);
            size_t off32 = ((size_t)((b * CH + h) * CS + s0 + r)) * 32;
            ((u32*)Oh)[off32 + lane] = hv;
            ((u32*)Ol)[off32 + lane] = lv;
        }
    } else {
        for (int c = wid; c < 64; c += 8) {
            size_t off32 = ((size_t)((b * CH + h) * CDK + c)) * (CS / 2) + s0 / 2;
#pragma unroll
            for (int j = 0; j < 2; j++) {
                int p = lane + 32 * j;
                float s0v = stage[(2 * p) * STAGE_LD + c];
                float s1v = stage[(2 * p + 1) * STAGE_LD + c];
                u32 hv, lv;
                split_pair(s0v, s1v, hv, lv);
                ((u32*)Vth)[off32 + p] = hv;
                ((u32*)Vtl)[off32 + p] = lv;
            }
        }
    }
}

// ---------------- Kernel: scores (z = h*2+b), u8 mask ----------------
__global__ void __launch_bounds__(256, 4) scores_kernel(
    const u16* __restrict__ Qh, const u16* __restrict__ Ql,
    const u16* __restrict__ Kh, const u16* __restrict__ Kl,
    const float* __restrict__ pos_bias, const u8* __restrict__ mask8,
    float* __restrict__ raw, float2* __restrict__ part)
{
    extern __shared__ char smem[];
    u32 sb = smem_u32(smem);
    const int tid = threadIdx.x, wid = tid >> 5, lane = tid & 31;
    const int kx = blockIdx.x, kk0 = kx * 64;
    const int q0 = blockIdx.y * 128;
    const int h = blockIdx.z >> 1, b = blockIdx.z & 1;
    const int bh = b * CH + h;

    cp_tile(sb, OFF_AH, OFF_AL,
            Qh + ((size_t)bh * CS + q0) * CDK,
            Ql + ((size_t)bh * CS + q0) * CDK, 128, CDK, tid);
    cp_tile(sb, OFF_BH, OFF_BL,
            Kh + ((size_t)bh * CS + kk0) * CDK,
            Kl + ((size_t)bh * CS + kk0) * CDK, 64, CDK, tid);
    CP_COMMIT();
    CP_WAIT(0);
    __syncthreads();

    float acc[2][4][4] = {};
    gemm_chunk(sb, OFF_AH, OFF_AL, OFF_BH, OFF_BL, wid, lane, acc);
    __syncthreads();
    float* stage = (float*)smem;
    store_stage(stage, acc, wid, lane);
    __syncthreads();

    const int halfl = lane >> 4;
    const int cq = (lane & 15) * 4;
#pragma unroll
    for (int it = 0; it < 8; it++) {
        const int r = wid * 16 + it * 2 + halfl;
        const int q = q0 + r;
        float4 pb = *(const float4*)(pos_bias + ((size_t)(h * CS + q)) * CS + kk0 + cq);
        u32 mk = *(const u32*)(mask8 + ((size_t)(b * CS + q)) * CS + kk0 + cq);
        float4 sv = *(const float4*)(stage + r * STAGE_LD + cq);
        float4 rv;
        rv.x = ((mk & 0x000000ffu) == 0) ? -1e9f : sv.x * 0.125f + pb.x;
        rv.y = ((mk & 0x0000ff00u) == 0) ? -1e9f : sv.y * 0.125f + pb.y;
        rv.z = ((mk & 0x00ff0000u) == 0) ? -1e9f : sv.z * 0.125f + pb.z;
        rv.w = ((mk & 0xff000000u) == 0) ? -1e9f : sv.w * 0.125f + pb.w;
        __stcs((float4*)(raw + ((size_t)(bh * CS + q)) * CS + kk0 + cq), rv);

        float mx = fmaxf(fmaxf(rv.x, rv.y), fmaxf(rv.z, rv.w));
#pragma unroll
        for (int o = 8; o > 0; o >>= 1) mx = fmaxf(mx, __shfl_xor_sync(0xffffffffu, mx, o));
        float se = __expf(rv.x - mx) + __expf(rv.y - mx) +
                   __expf(rv.z - mx) + __expf(rv.w - mx);
#pragma unroll
        for (int o = 8; o > 0; o >>= 1) se += __shfl_xor_sync(0xffffffffu, se, o);
        if ((lane & 15) == 0)
            part[((size_t)(bh * CS + q)) * 32 + kx] = make_float2(mx, se);
    }
}

// ---------------- Kernel: reduce partials -> (max, 1/sum) ----------------
__global__ void __launch_bounds__(256) reduce_kernel(
    const float2* __restrict__ part, float2* __restrict__ stats)
{
    const int wid = threadIdx.x >> 5, lane = threadIdx.x & 31;
    const int row = blockIdx.x * 8 + wid;
    float2 p = part[(size_t)row * 32 + lane];
    float M = p.x;
#pragma unroll
    for (int o = 16; o > 0; o >>= 1) M = fmaxf(M, __shfl_xor_sync(0xffffffffu, M, o));
    float s = p.y * __expf(p.x - M);
#pragma unroll
    for (int o = 16; o > 0; o >>= 1) s += __shfl_xor_sync(0xffffffffu, s, o);
    if (lane == 0) stats[row] = make_float2(M, 1.0f / s);
}

// ---------------- Kernel: PV split-K (single V buffer, 4 blocks/SM) ----------------
__global__ void __launch_bounds__(256, 4) pv_kernel(
    float* __restrict__ attn,
    const u16* __restrict__ Vth, const u16* __restrict__ Vtl,
    const float2* __restrict__ stats,
    float* __restrict__ ctx0, float* __restrict__ ctx1)
{
    extern __shared__ char smem[];
    u32 sb = smem_u32(smem);
    const int tid = threadIdx.x, wid = tid >> 5, lane = tid & 31;
    const int q0 = blockIdx.x * 128;
    const int kseg = blockIdx.y;
    const int bh = blockIdx.z;
    const int kbase = kseg * 16;

    float* smax = (float*)(smem + PV_STATS);
    float* sinv = smax + 128;
    if (tid < 128) {
        float2 st = stats[(size_t)bh * CS + q0 + tid];
        smax[tid] = st.x;
        sinv[tid] = st.y;
    }
    cp_tile(sb, PV_VHO, PV_VLO,
            Vth + (size_t)bh * CDK * CS + kbase * 64,
            Vtl + (size_t)bh * CDK * CS + kbase * 64, 64, CS, tid);
    CP_COMMIT();
    __syncthreads();

    const int rb = tid >> 4, cg = (tid & 15) * 4;
    float acc[2][4][4] = {};
    for (int i = 0; i < 16; i++) {
        const int kc = kbase + i;
#pragma unroll
        for (int p = 0; p < 8; p++) {
            int row = p * 16 + rb;
            size_t ao = ((size_t)(bh * CS + q0 + row)) * CS + kc * 64 + cg;
            float4 rv = __ldcs((const float4*)(attn + ao));
            float mx = smax[row], iv = sinv[row];
            float4 pw;
            pw.x = __expf(rv.x - mx) * iv;
            pw.y = __expf(rv.y - mx) * iv;
            pw.z = __expf(rv.z - mx) * iv;
            pw.w = __expf(rv.w - mx) * iv;
            __stcs((float4*)(attn + ao), pw);
            uint2 hv, lv;
            split_pair(pw.x, pw.y, hv.x, lv.x);
            split_pair(pw.z, pw.w, hv.y, lv.y);
            u32 off = (u32)(row * (LDAB * 2) + cg * 2);
            *(uint2*)(smem + PV_PH + off) = hv;
            *(uint2*)(smem + PV_PL + off) = lv;
        }
        CP_WAIT(0);
        __syncthreads();
        gemm_chunk(sb, PV_PH, PV_PL, PV_VHO, PV_VLO, wid, lane, acc);
        __syncthreads();
        if (i < 15) {
            cp_tile(sb, PV_VHO, PV_VLO,
                    Vth + (size_t)bh * CDK * CS + (kc + 1) * 64,
                    Vtl + (size_t)bh * CDK * CS + (kc + 1) * 64, 64, CS, tid);
            CP_COMMIT();
        }
    }

    float* stage = (float*)smem;
    store_stage(stage, acc, wid, lane);
    __syncthreads();

    float* ctx = kseg ? ctx1 : ctx0;
    const int b = bh / CH, h = bh - b * CH;
    for (int r = wid; r < 128; r += 8) {
        size_t off = ((size_t)(b * CS + q0 + r)) * CD + h * CDK;
        ctx[off + lane]      = stage[r * STAGE_LD + lane];
        ctx[off + 32 + lane] = stage[r * STAGE_LD + 32 + lane];
    }
}

// ---------------- Kernel: output projection (pre-split Wo via cp.async) ----------------
__global__ void __launch_bounds__(256) outproj_kernel(
    const float* __restrict__ ctx0, const float* __restrict__ ctx1,
    const u16* __restrict__ Wh, const u16* __restrict__ Wl,
    const float* __restrict__ bias, float* __restrict__ out)
{
    extern __shared__ char smem[];
    u32 sb = smem_u32(smem);
    const int tid = threadIdx.x, wid = tid >> 5, lane = tid & 31;
    const int n0 = blockIdx.x * 64, m0 = blockIdx.y * 128;

    const u16* wh = Wh + (size_t)3 * CD * CD + (size_t)n0 * CD;
    const u16* wl = Wl + (size_t)3 * CD * CD + (size_t)n0 * CD;

    float acc[2][4][4] = {};
    for (int kc = 0; kc < 12; kc++) {
        cp_tile(sb, OFF_BH, OFF_BL, wh + kc * 64, wl + kc * 64, 64, CD, tid);
        CP_COMMIT();
        fill_split2(smem, OFF_AH, OFF_AL,
                    ctx0 + (size_t)m0 * CD + kc * 64,
                    ctx1 + (size_t)m0 * CD + kc * 64, 128, CD, tid);
        CP_WAIT(0);
        __syncthreads();
        gemm_chunk(sb, OFF_AH, OFF_AL, OFF_BH, OFF_BL, wid, lane, acc);
        __syncthreads();
    }
    float* stage = (float*)smem;
    store_stage(stage, acc, wid, lane);
    __syncthreads();

    float b0 = bias[n0 + lane];
    float b1 = bias[n0 + 32 + lane];
    for (int r = wid; r < 128; r += 8) {
        size_t off = (size_t)(m0 + r) * CD + n0;
        out[off + lane]      = stage[r * STAGE_LD + lane] + b0;
        out[off + 32 + lane] = stage[r * STAGE_LD + 32 + lane] + b1;
    }
}

// ---------------------------------------------------------------------------
extern "C" void kernel_launch(void* const* d_in, const int* in_sizes, int n_in,
                              void* d_out, int out_size)
{
    (void)in_sizes; (void)n_in; (void)out_size;
    const float* query    = (const float*)d_in[0];
    const float* key      = (const float*)d_in[1];
    const float* value    = (const float*)d_in[2];
    const int*   mask     = (const int*)d_in[3];
    const float* pos_bias = (const float*)d_in[4];
    const float* Wq       = (const float*)d_in[5];
    const float* Wk       = (const float*)d_in[6];
    const float* Wv       = (const float*)d_in[7];
    const float* Wo       = (const float*)d_in[8];
    const float* bo       = (const float*)d_in[9];

    float* out  = (float*)d_out;
    float* attn = out + OUT_ELEMS;

    u16 *pXh, *pXl, *pWh, *pWl, *pQh, *pQl, *pKh, *pKl, *pVth, *pVtl;
    u8* pM8;
    float *pC0, *pC1;
    float2 *pPart, *pStats;
    cudaGetSymbolAddress((void**)&pXh,  g_Xh);
    cudaGetSymbolAddress((void**)&pXl,  g_Xl);
    cudaGetSymbolAddress((void**)&pWh,  g_Wh);
    cudaGetSymbolAddress((void**)&pWl,  g_Wl);
    cudaGetSymbolAddress((void**)&pQh,  g_Qh);
    cudaGetSymbolAddress((void**)&pQl,  g_Ql);
    cudaGetSymbolAddress((void**)&pKh,  g_Kh);
    cudaGetSymbolAddress((void**)&pKl,  g_Kl);
    cudaGetSymbolAddress((void**)&pVth, g_Vth);
    cudaGetSymbolAddress((void**)&pVtl, g_Vtl);
    cudaGetSymbolAddress((void**)&pM8,  g_mask8);
    cudaGetSymbolAddress((void**)&pC0,  g_ctx0);
    cudaGetSymbolAddress((void**)&pC1,  g_ctx1);
    cudaGetSymbolAddress((void**)&pPart,  g_part);
    cudaGetSymbolAddress((void**)&pStats, g_stats);

    cudaFuncSetAttribute(proj_kernel,    cudaFuncAttributeMaxDynamicSharedMemorySize, PR_SMEM);
    cudaFuncSetAttribute(scores_kernel,  cudaFuncAttributeMaxDynamicSharedMemorySize, PR_SMEM);
    cudaFuncSetAttribute(pv_kernel,      cudaFuncAttributeMaxDynamicSharedMemorySize, PV_SMEM);
    cudaFuncSetAttribute(outproj_kernel, cudaFuncAttributeMaxDynamicSharedMemorySize, PR_SMEM);

    // pre-split inputs/weights; convert mask to u8
    const int nX4 = CM * CD / 4;   // 786432
    const int nW4 = CD * CD / 4;   // 147456
    const int nM4 = CB * CS * CS / 4;
    dim3 gSX((nX4 + 255) / 256, 3);
    splitx_kernel<<<gSX, 256>>>(query, key, value, pXh, pXl, nX4);
    dim3 gSW((nW4 + 255) / 256, 4);
    splitw_kernel<<<gSW, 256>>>(Wq, Wk, Wv, Wo, pWh, pWl, nW4);
    mask8_kernel<<<(nM4 + 255) / 256, 256>>>(mask, pM8, nM4);

    dim3 gProj(CD / 64, CM / 128, 3);          // (12, 32, 3)
    proj_kernel<<<gProj, 256, PR_SMEM>>>(pXh, pXl, pWh, pWl,
                                         pQh, pQl, pKh, pKl, pVth, pVtl);

    dim3 gScores(CS / 64, CS / 128, CBH);      // (32, 16, 24), z = h*2+b
    scores_kernel<<<gScores, 256, PR_SMEM>>>(pQh, pQl, pKh, pKl,
                                             pos_bias, pM8, attn, pPart);

    reduce_kernel<<<BHS / 8, 256>>>(pPart, pStats);

    dim3 gPV(CS / 128, 2, CBH);                // (16, 2, 24) split-K
    pv_kernel<<<gPV, 256, PV_SMEM>>>(attn, pVth, pVtl, pStats, pC0, pC1);

    dim3 gOut(CD / 64, CM / 128);              // (12, 32)
    outproj_kernel<<<gOut, 256, PR_SMEM>>>(pC0, pC1, pWh, pWl, bo, out);
}